// round 2
// baseline (speedup 1.0000x reference)
#include <cuda_runtime.h>

#define N_NODES 100000
#define N_EDGES 1600000
#define IN_DIM 128
#define HID 256
#define EPS 1e-5f

// ---------------- scratch (static __device__ — no runtime allocation) ----------------
__device__ float g_agg[N_NODES * HID];     // aggregation buffer / classifier z buffer
__device__ float g_h1[N_NODES * HID];
__device__ float g_h2[N_NODES * HID];
__device__ int   g_cnt[N_NODES];
__device__ int   g_cursor[N_NODES];
__device__ int   g_scantmp[N_NODES];
__device__ int   g_rowptr[N_NODES + 1];
__device__ int   g_adj[N_EDGES];
__device__ int   g_bsum[128];
__device__ float g_colsum[HID];
__device__ float g_colsumsq[HID];
__device__ float g_na[HID];
__device__ float g_nc[HID];

// ---------------- CSR build ----------------
__global__ void k_init() {
    int i = blockIdx.x * blockDim.x + threadIdx.x;
    if (i < N_NODES) { g_cnt[i] = 0; g_cursor[i] = 0; }
    if (i < HID)     { g_colsum[i] = 0.f; g_colsumsq[i] = 0.f; }
}

__global__ void k_hist(const int* __restrict__ dst) {
    int e = blockIdx.x * blockDim.x + threadIdx.x;
    if (e < N_EDGES) atomicAdd(&g_cnt[dst[e]], 1);
}

__global__ void k_scan1() {
    __shared__ int s[1024];
    int i = blockIdx.x * 1024 + threadIdx.x;
    int v = (i < N_NODES) ? g_cnt[i] : 0;
    s[threadIdx.x] = v;
    __syncthreads();
    #pragma unroll
    for (int off = 1; off < 1024; off <<= 1) {
        int t = (threadIdx.x >= off) ? s[threadIdx.x - off] : 0;
        __syncthreads();
        s[threadIdx.x] += t;
        __syncthreads();
    }
    if (i < N_NODES) g_scantmp[i] = s[threadIdx.x];
    if (threadIdx.x == 1023) g_bsum[blockIdx.x] = s[1023];
}

__global__ void k_scan2(int nb) {
    if (threadIdx.x == 0 && blockIdx.x == 0) {
        int acc = 0;
        for (int i = 0; i < nb; i++) { int v = g_bsum[i]; g_bsum[i] = acc; acc += v; }
    }
}

__global__ void k_scan3() {
    int i = blockIdx.x * 1024 + threadIdx.x;
    if (i < N_NODES) {
        g_rowptr[i + 1] = g_scantmp[i] + g_bsum[blockIdx.x];
        if (i == 0) g_rowptr[0] = 0;
    }
}

__global__ void k_fill(const int* __restrict__ src, const int* __restrict__ dst) {
    int e = blockIdx.x * blockDim.x + threadIdx.x;
    if (e < N_EDGES) {
        int d = dst[e];
        int pos = g_rowptr[d] + atomicAdd(&g_cursor[d], 1);
        g_adj[pos] = src[e];
    }
}

// ---------------- mean aggregation (warp per node, gather, no float atomics) ----------------
template <int D>
__global__ void k_agg(const float* __restrict__ x, float* __restrict__ agg) {
    int w = (blockIdx.x * blockDim.x + threadIdx.x) >> 5;
    int lane = threadIdx.x & 31;
    if (w >= N_NODES) return;
    int s0 = g_rowptr[w], s1 = g_rowptr[w + 1];
    float4 a0 = make_float4(0.f, 0.f, 0.f, 0.f);
    float4 a1 = make_float4(0.f, 0.f, 0.f, 0.f);
    int e = s0;
    for (; e + 2 <= s1; e += 2) {
        int na = g_adj[e], nb = g_adj[e + 1];
        const float4* pa = (const float4*)(x + (size_t)na * D);
        const float4* pb = (const float4*)(x + (size_t)nb * D);
        float4 va = pa[lane], vb = pb[lane];
        a0.x += va.x + vb.x; a0.y += va.y + vb.y;
        a0.z += va.z + vb.z; a0.w += va.w + vb.w;
        if (D == 256) {
            float4 va1 = pa[lane + 32], vb1 = pb[lane + 32];
            a1.x += va1.x + vb1.x; a1.y += va1.y + vb1.y;
            a1.z += va1.z + vb1.z; a1.w += va1.w + vb1.w;
        }
    }
    if (e < s1) {
        int na = g_adj[e];
        const float4* pa = (const float4*)(x + (size_t)na * D);
        float4 va = pa[lane];
        a0.x += va.x; a0.y += va.y; a0.z += va.z; a0.w += va.w;
        if (D == 256) {
            float4 va1 = pa[lane + 32];
            a1.x += va1.x; a1.y += va1.y; a1.z += va1.z; a1.w += va1.w;
        }
    }
    int deg = s1 - s0;
    float inv = 1.f / (float)(deg > 0 ? deg : 1);
    a0.x *= inv; a0.y *= inv; a0.z *= inv; a0.w *= inv;
    float4* o = (float4*)(agg + (size_t)w * D);
    o[lane] = a0;
    if (D == 256) {
        a1.x *= inv; a1.y *= inv; a1.z *= inv; a1.w *= inv;
        o[lane + 32] = a1;
    }
}

// ---------------- SGEMM: C = A1@W1 (+ A2@W2) + bias, optional stats / relu ----------------
// MODE 0: dual A (K total = 2*D), add bias, accumulate column sum/sumsq (pre-norm h)
// MODE 1: single A (K = D), add bias + relu (classifier hidden layer)
template <int MODE>
__global__ __launch_bounds__(256, 2)
void k_gemm(const float* __restrict__ A1, const float* __restrict__ W1,
            const float* __restrict__ A2, const float* __restrict__ W2,
            const float* __restrict__ bias, float* __restrict__ C,
            int D, int NW) {
    const int BM = 128, BN = 128, BK = 16;
    __shared__ float As[BK][BM + 4];
    __shared__ float Bs[BK][BN];
    __shared__ float scol[BN], scolq[BN];
    int tid = threadIdx.x;
    int bm0 = blockIdx.y * BM, bn0 = blockIdx.x * BN;
    int ty = tid >> 4, tx = tid & 15;

    float acc[8][8];
    #pragma unroll
    for (int i = 0; i < 8; i++)
        #pragma unroll
        for (int j = 0; j < 8; j++) acc[i][j] = 0.f;

    int Ktot = (MODE == 0) ? 2 * D : D;
    for (int kb = 0; kb < Ktot; kb += BK) {
        const float* A; const float* W; int kk;
        if (MODE == 0 && kb >= D) { A = A2; W = W2; kk = kb - D; }
        else                      { A = A1; W = W1; kk = kb; }
        // A tile -> As (transposed)
        #pragma unroll
        for (int r = 0; r < 2; r++) {
            int i = tid + r * 256;
            int row = i >> 2, c4 = i & 3;
            float4 v = make_float4(0.f, 0.f, 0.f, 0.f);
            int gr = bm0 + row;
            if (gr < N_NODES) v = *(const float4*)(A + (size_t)gr * D + kk + c4 * 4);
            As[c4 * 4 + 0][row] = v.x;
            As[c4 * 4 + 1][row] = v.y;
            As[c4 * 4 + 2][row] = v.z;
            As[c4 * 4 + 3][row] = v.w;
        }
        // W tile -> Bs
        #pragma unroll
        for (int r = 0; r < 2; r++) {
            int i = tid + r * 256;
            int kr = i >> 5, n4 = i & 31;
            float4 v = *(const float4*)(W + (size_t)(kk + kr) * NW + bn0 + n4 * 4);
            *(float4*)&Bs[kr][n4 * 4] = v;
        }
        __syncthreads();
        #pragma unroll
        for (int k2 = 0; k2 < BK; k2++) {
            float a[8], b[8];
            *(float4*)&a[0] = *(float4*)&As[k2][ty * 8];
            *(float4*)&a[4] = *(float4*)&As[k2][ty * 8 + 4];
            *(float4*)&b[0] = *(float4*)&Bs[k2][tx * 8];
            *(float4*)&b[4] = *(float4*)&Bs[k2][tx * 8 + 4];
            #pragma unroll
            for (int i = 0; i < 8; i++)
                #pragma unroll
                for (int j = 0; j < 8; j++)
                    acc[i][j] += a[i] * b[j];
        }
        __syncthreads();
    }

    float bj[8];
    #pragma unroll
    for (int j = 0; j < 8; j++) bj[j] = bias[bn0 + tx * 8 + j];
    float cs[8], cq[8];
    #pragma unroll
    for (int j = 0; j < 8; j++) { cs[j] = 0.f; cq[j] = 0.f; }

    #pragma unroll
    for (int i = 0; i < 8; i++) {
        int gr = bm0 + ty * 8 + i;
        if (gr < N_NODES) {
            float h[8];
            #pragma unroll
            for (int j = 0; j < 8; j++) {
                h[j] = acc[i][j] + bj[j];
                if (MODE == 1) h[j] = fmaxf(h[j], 0.f);
            }
            float4 s0 = make_float4(h[0], h[1], h[2], h[3]);
            float4 s1 = make_float4(h[4], h[5], h[6], h[7]);
            float* cp = C + (size_t)gr * NW + bn0 + tx * 8;
            *(float4*)cp = s0;
            *(float4*)(cp + 4) = s1;
            if (MODE == 0) {
                #pragma unroll
                for (int j = 0; j < 8; j++) { cs[j] += h[j]; cq[j] += h[j] * h[j]; }
            }
        }
    }

    if (MODE == 0) {
        if (tid < BN) { scol[tid] = 0.f; scolq[tid] = 0.f; }
        __syncthreads();
        #pragma unroll
        for (int j = 0; j < 8; j++) {
            atomicAdd(&scol[tx * 8 + j], cs[j]);
            atomicAdd(&scolq[tx * 8 + j], cq[j]);
        }
        __syncthreads();
        if (tid < BN) {
            atomicAdd(&g_colsum[bn0 + tid], scol[tid]);
            atomicAdd(&g_colsumsq[bn0 + tid], scolq[tid]);
        }
    }
}

// ---------------- batchnorm stats -> affine (a, c); re-zero accumulators ----------------
__global__ void k_stats(const float* __restrict__ g, const float* __restrict__ be) {
    int j = threadIdx.x;
    if (j < HID) {
        float mu  = g_colsum[j] / (float)N_NODES;
        float var = g_colsumsq[j] / (float)N_NODES - mu * mu;
        var = fmaxf(var, 0.f);
        float a = g[j] * rsqrtf(var + EPS);
        g_na[j] = a;
        g_nc[j] = be[j] - mu * a;
        g_colsum[j] = 0.f;
        g_colsumsq[j] = 0.f;
    }
}

// ---------------- elementwise normalize + relu (in place) ----------------
__global__ void k_normrelu(float* __restrict__ h) {
    int i = blockIdx.x * blockDim.x + threadIdx.x;   // float4 index
    if (i >= (N_NODES * HID) / 4) return;
    float4 v = ((float4*)h)[i];
    int c = (i * 4) & (HID - 1);
    v.x = fmaxf(v.x * g_na[c + 0] + g_nc[c + 0], 0.f);
    v.y = fmaxf(v.y * g_na[c + 1] + g_nc[c + 1], 0.f);
    v.z = fmaxf(v.z * g_na[c + 2] + g_nc[c + 2], 0.f);
    v.w = fmaxf(v.w * g_na[c + 3] + g_nc[c + 3], 0.f);
    ((float4*)h)[i] = v;
}

// ---------------- final tiny GEMV: out[n, 2] = z @ cw2 + cb2 (warp per row) ----------------
__global__ void k_final(const float* __restrict__ z, const float* __restrict__ cw2,
                        const float* __restrict__ cb2, float* __restrict__ out) {
    int w = (blockIdx.x * blockDim.x + threadIdx.x) >> 5;
    int lane = threadIdx.x & 31;
    if (w >= N_NODES) return;
    float4 v = ((const float4*)(z + (size_t)w * 128))[lane];
    int k = lane * 4;
    float o0 = v.x * cw2[(k + 0) * 2 + 0] + v.y * cw2[(k + 1) * 2 + 0]
             + v.z * cw2[(k + 2) * 2 + 0] + v.w * cw2[(k + 3) * 2 + 0];
    float o1 = v.x * cw2[(k + 0) * 2 + 1] + v.y * cw2[(k + 1) * 2 + 1]
             + v.z * cw2[(k + 2) * 2 + 1] + v.w * cw2[(k + 3) * 2 + 1];
    #pragma unroll
    for (int off = 16; off; off >>= 1) {
        o0 += __shfl_down_sync(0xffffffffu, o0, off);
        o1 += __shfl_down_sync(0xffffffffu, o1, off);
    }
    if (lane == 0) {
        out[2 * w + 0] = o0 + cb2[0];
        out[2 * w + 1] = o1 + cb2[1];
    }
}

// ---------------- launch ----------------
extern "C" void kernel_launch(void* const* d_in, const int* in_sizes, int n_in,
                              void* d_out, int out_size) {
    const float* x    = (const float*)d_in[0];
    const int*   ei   = (const int*)d_in[1];   // int32! (JAX x64 disabled)
    const int*   srcv = ei;
    const int*   dstv = ei + N_EDGES;
    const float* wl0 = (const float*)d_in[2];
    const float* wr0 = (const float*)d_in[3];
    const float* b0  = (const float*)d_in[4];
    const float* g0  = (const float*)d_in[5];
    const float* be0 = (const float*)d_in[6];
    const float* wl1 = (const float*)d_in[7];
    const float* wr1 = (const float*)d_in[8];
    const float* b1  = (const float*)d_in[9];
    const float* g1  = (const float*)d_in[10];
    const float* be1 = (const float*)d_in[11];
    const float* wl2 = (const float*)d_in[12];
    const float* wr2 = (const float*)d_in[13];
    const float* b2  = (const float*)d_in[14];
    const float* g2  = (const float*)d_in[15];
    const float* be2 = (const float*)d_in[16];
    const float* cw1 = (const float*)d_in[17];
    const float* cb1 = (const float*)d_in[18];
    const float* cw2 = (const float*)d_in[19];
    const float* cb2 = (const float*)d_in[20];
    float* out = (float*)d_out;

    float *agg, *h1, *h2;
    cudaGetSymbolAddress((void**)&agg, g_agg);
    cudaGetSymbolAddress((void**)&h1,  g_h1);
    cudaGetSymbolAddress((void**)&h2,  g_h2);

    // CSR build (once per launch, reused by all 3 layers)
    k_init<<<(N_NODES + 255) / 256, 256>>>();
    k_hist<<<(N_EDGES + 255) / 256, 256>>>(dstv);
    int nb = (N_NODES + 1023) / 1024;
    k_scan1<<<nb, 1024>>>();
    k_scan2<<<1, 32>>>(nb);
    k_scan3<<<nb, 1024>>>();
    k_fill<<<(N_EDGES + 255) / 256, 256>>>(srcv, dstv);

    dim3 ggrid(2, (N_NODES + 127) / 128);
    int  aggGrid = (N_NODES * 32 + 255) / 256;
    int  nrGrid  = (N_NODES * HID / 4 + 255) / 256;

    // layer 0 (D = 128)
    k_agg<IN_DIM><<<aggGrid, 256>>>(x, agg);
    k_gemm<0><<<ggrid, 256>>>(agg, wl0, x, wr0, b0, h1, IN_DIM, HID);
    k_stats<<<1, 256>>>(g0, be0);
    k_normrelu<<<nrGrid, 256>>>(h1);

    // layer 1 (D = 256)
    k_agg<HID><<<aggGrid, 256>>>(h1, agg);
    k_gemm<0><<<ggrid, 256>>>(agg, wl1, h1, wr1, b1, h2, HID, HID);
    k_stats<<<1, 256>>>(g1, be1);
    k_normrelu<<<nrGrid, 256>>>(h2);

    // layer 2 (D = 256)
    k_agg<HID><<<aggGrid, 256>>>(h2, agg);
    k_gemm<0><<<ggrid, 256>>>(agg, wl2, h2, wr2, b2, h1, HID, HID);
    k_stats<<<1, 256>>>(g2, be2);
    k_normrelu<<<nrGrid, 256>>>(h1);

    // classifier: z = relu(h1 @ cw1 + cb1)  [100000, 128] -> reuse agg buffer
    dim3 cgrid(1, (N_NODES + 127) / 128);
    k_gemm<1><<<cgrid, 256>>>(h1, cw1, nullptr, nullptr, cb1, agg, HID, 128);
    k_final<<<aggGrid, 256>>>(agg, cw2, cb2, out);
}

// round 4
// speedup vs baseline: 1.9428x; 1.9428x over previous
#include <cuda_runtime.h>
#include <cuda_bf16.h>
#include <cstdint>

#define N_NODES 100000
#define N_EDGES 1600000
#define IN_DIM 128
#define HID 256
#define EPS 1e-5f

// ======================= scratch (static __device__) =======================
__device__ float g_hraw[N_NODES * HID];                 // GEMM output fp32 / classifier z
__device__ __nv_bfloat16 g_ah[N_NODES * HID];           // agg hi
__device__ __nv_bfloat16 g_al[N_NODES * HID];           // agg lo
__device__ __nv_bfloat16 g_bh1[N_NODES * HID];          // buf A hi
__device__ __nv_bfloat16 g_bl1[N_NODES * HID];          // buf A lo
__device__ __nv_bfloat16 g_bh2[N_NODES * HID];          // buf B hi
__device__ __nv_bfloat16 g_bl2[N_NODES * HID];          // buf B lo
__device__ __nv_bfloat16 g_w[720896];                   // converted weights W^T [N][K] hi/lo
__device__ int   g_cnt[N_NODES];
__device__ int   g_cursor[N_NODES];
__device__ int   g_scantmp[N_NODES];
__device__ int   g_rowptr[N_NODES + 1];
__device__ int   g_adj[N_EDGES];
__device__ int   g_bsum[128];
__device__ float g_colsum[HID];
__device__ float g_colsumsq[HID];
__device__ float g_na[HID];
__device__ float g_nc[HID];

// weight pool offsets (elements)
#define WL0H 0
#define WL0L 32768
#define WR0H 65536
#define WR0L 98304
#define WL1H 131072
#define WL1L 196608
#define WR1H 262144
#define WR1L 327680
#define WL2H 393216
#define WL2L 458752
#define WR2H 524288
#define WR2L 589824
#define CW1H 655360
#define CW1L 688128

__device__ __forceinline__ uint32_t smem_u32(const void* p) {
    uint32_t a;
    asm("{ .reg .u64 t; cvta.to.shared.u64 t, %1; cvt.u32.u64 %0, t; }" : "=r"(a) : "l"(p));
    return a;
}

// ======================= CSR build =======================
__global__ void k_init() {
    int i = blockIdx.x * blockDim.x + threadIdx.x;
    if (i < N_NODES) { g_cnt[i] = 0; g_cursor[i] = 0; }
    if (i < HID)     { g_colsum[i] = 0.f; g_colsumsq[i] = 0.f; }
}
__global__ void k_hist(const int* __restrict__ dst) {
    int e = blockIdx.x * blockDim.x + threadIdx.x;
    if (e < N_EDGES) atomicAdd(&g_cnt[dst[e]], 1);
}
__global__ void k_scan1() {
    __shared__ int s[1024];
    int i = blockIdx.x * 1024 + threadIdx.x;
    int v = (i < N_NODES) ? g_cnt[i] : 0;
    s[threadIdx.x] = v;
    __syncthreads();
    #pragma unroll
    for (int off = 1; off < 1024; off <<= 1) {
        int t = (threadIdx.x >= off) ? s[threadIdx.x - off] : 0;
        __syncthreads();
        s[threadIdx.x] += t;
        __syncthreads();
    }
    if (i < N_NODES) g_scantmp[i] = s[threadIdx.x];
    if (threadIdx.x == 1023) g_bsum[blockIdx.x] = s[1023];
}
__global__ void k_scan2(int nb) {
    if (threadIdx.x == 0 && blockIdx.x == 0) {
        int acc = 0;
        for (int i = 0; i < nb; i++) { int v = g_bsum[i]; g_bsum[i] = acc; acc += v; }
    }
}
__global__ void k_scan3() {
    int i = blockIdx.x * 1024 + threadIdx.x;
    if (i < N_NODES) {
        g_rowptr[i + 1] = g_scantmp[i] + g_bsum[blockIdx.x];
        if (i == 0) g_rowptr[0] = 0;
    }
}
__global__ void k_fill(const int* __restrict__ src, const int* __restrict__ dst) {
    int e = blockIdx.x * blockDim.x + threadIdx.x;
    if (e < N_EDGES) {
        int d = dst[e];
        int pos = g_rowptr[d] + atomicAdd(&g_cursor[d], 1);
        g_adj[pos] = src[e];
    }
}

// ======================= bf16 pack helpers =======================
__device__ __forceinline__ uint32_t pack2bf(float a, float b) {
    uint16_t ua = __bfloat16_as_ushort(__float2bfloat16(a));
    uint16_t ub = __bfloat16_as_ushort(__float2bfloat16(b));
    return (uint32_t)ua | ((uint32_t)ub << 16);
}
__device__ __forceinline__ float lo_of(float v) {
    return v - __bfloat162float(__float2bfloat16(v));
}

// ======================= aggregation =======================
__global__ void k_agg_f32(const float* __restrict__ x,
                          __nv_bfloat16* __restrict__ oh, __nv_bfloat16* __restrict__ ol) {
    int w = (blockIdx.x * blockDim.x + threadIdx.x) >> 5;
    int lane = threadIdx.x & 31;
    if (w >= N_NODES) return;
    int s0 = g_rowptr[w], s1 = g_rowptr[w + 1];
    float4 a0 = make_float4(0.f, 0.f, 0.f, 0.f);
    for (int e = s0; e < s1; e++) {
        const float4* p = (const float4*)(x + (size_t)g_adj[e] * IN_DIM);
        float4 v = p[lane];
        a0.x += v.x; a0.y += v.y; a0.z += v.z; a0.w += v.w;
    }
    int deg = s1 - s0;
    float inv = 1.f / (float)(deg > 0 ? deg : 1);
    a0.x *= inv; a0.y *= inv; a0.z *= inv; a0.w *= inv;
    size_t base = (size_t)w * IN_DIM + lane * 4;
    uint2 uh, ul;
    uh.x = pack2bf(a0.x, a0.y); uh.y = pack2bf(a0.z, a0.w);
    ul.x = pack2bf(lo_of(a0.x), lo_of(a0.y)); ul.y = pack2bf(lo_of(a0.z), lo_of(a0.w));
    *(uint2*)(oh + base) = uh;
    *(uint2*)(ol + base) = ul;
}

__global__ void k_agg_bf16(const __nv_bfloat16* __restrict__ xh, const __nv_bfloat16* __restrict__ xl,
                           __nv_bfloat16* __restrict__ oh, __nv_bfloat16* __restrict__ ol) {
    int w = (blockIdx.x * blockDim.x + threadIdx.x) >> 5;
    int lane = threadIdx.x & 31;
    if (w >= N_NODES) return;
    int s0 = g_rowptr[w], s1 = g_rowptr[w + 1];
    float acc[8];
    #pragma unroll
    for (int i = 0; i < 8; i++) acc[i] = 0.f;
    for (int e = s0; e < s1; e++) {
        size_t base = (size_t)g_adj[e] * HID + lane * 8;
        uint4 vh = *(const uint4*)(xh + base);
        uint4 vl = *(const uint4*)(xl + base);
        const uint32_t* ph = &vh.x;
        const uint32_t* pl = &vl.x;
        #pragma unroll
        for (int i = 0; i < 4; i++) {
            float2 fh = __bfloat1622float2(*(const __nv_bfloat162*)&ph[i]);
            float2 fl = __bfloat1622float2(*(const __nv_bfloat162*)&pl[i]);
            acc[i * 2 + 0] += fh.x + fl.x;
            acc[i * 2 + 1] += fh.y + fl.y;
        }
    }
    int deg = s1 - s0;
    float inv = 1.f / (float)(deg > 0 ? deg : 1);
    uint4 uh, ul;
    uint32_t* ph = &uh.x; uint32_t* pl = &ul.x;
    #pragma unroll
    for (int i = 0; i < 4; i++) {
        float v0 = acc[i * 2] * inv, v1 = acc[i * 2 + 1] * inv;
        ph[i] = pack2bf(v0, v1);
        pl[i] = pack2bf(lo_of(v0), lo_of(v1));
    }
    size_t base = (size_t)w * HID + lane * 8;
    *(uint4*)(oh + base) = uh;
    *(uint4*)(ol + base) = ul;
}

// ======================= conversions =======================
__global__ void k_convx(const float* __restrict__ x,
                        __nv_bfloat16* __restrict__ oh, __nv_bfloat16* __restrict__ ol) {
    int i = blockIdx.x * blockDim.x + threadIdx.x;   // float4 index
    if (i >= N_NODES * IN_DIM / 4) return;
    float4 v = ((const float4*)x)[i];
    uint2 uh, ul;
    uh.x = pack2bf(v.x, v.y); uh.y = pack2bf(v.z, v.w);
    ul.x = pack2bf(lo_of(v.x), lo_of(v.y)); ul.y = pack2bf(lo_of(v.z), lo_of(v.w));
    ((uint2*)oh)[i] = uh;
    ((uint2*)ol)[i] = ul;
}

// W fp32 [K,N] -> W^T bf16 [N][K] hi/lo
__global__ void k_convw(const float* __restrict__ W, __nv_bfloat16* __restrict__ oh,
                        __nv_bfloat16* __restrict__ ol, int K, int N) {
    int id = blockIdx.x * blockDim.x + threadIdx.x;
    if (id >= K * N) return;
    int k = id / N, n = id % N;
    float v = W[id];
    size_t pos = (size_t)n * K + k;
    oh[pos] = __float2bfloat16(v);
    ol[pos] = __float2bfloat16(lo_of(v));
}

// ======================= bf16 mma.sync GEMM =======================
// C[M, NT] = sum_seg A_seg[M, D] @ W_seg^T  + bias (optional relu)
// A_seg row-major [N_NODES, D] bf16; W_seg = W^T row-major [NT, D] bf16
struct GemmSegs { const __nv_bfloat16* A[6]; const __nv_bfloat16* W[6]; };

#define MMA_BF16(c, a, b0v, b1v) \
    asm volatile("mma.sync.aligned.m16n8k16.row.col.f32.bf16.bf16.f32 " \
        "{%0,%1,%2,%3}, {%4,%5,%6,%7}, {%8,%9}, {%0,%1,%2,%3};" \
        : "+f"((c)[0]), "+f"((c)[1]), "+f"((c)[2]), "+f"((c)[3]) \
        : "r"((a)[0]), "r"((a)[1]), "r"((a)[2]), "r"((a)[3]), "r"(b0v), "r"(b1v))

template <int NT>
__global__ __launch_bounds__(256, 2)
void k_mma(GemmSegs segs, int nseg, int D, const float* __restrict__ bias,
           float* __restrict__ C, int relu) {
    extern __shared__ char dsm[];                 // [2 stages][A 16KB | B 16KB]
    const uint32_t sb = smem_u32(dsm);
    const int tid = threadIdx.x;
    const int lane = tid & 31, wid = tid >> 5;
    const int wm = wid & 3, wn = wid >> 2;        // 4 m-warps x 2 n-warps
    const int bm0 = blockIdx.y * 128, bn0 = blockIdx.x * 128;
    const int grp = lane >> 3, tg = lane & 7;

    const int cpsLog = (D == 256) ? 2 : 1;        // k64-blocks per segment (log2)
    const int nkb = nseg << cpsLog;

    // ldmatrix per-thread geometry (XOR-swizzled 128B rows)
    const uint32_t xr = (uint32_t)tg << 4;
    const int rowA0 = wm * 32 + tg + (grp & 1) * 8;
    const int rowB0 = wn * 64 + tg + (grp >> 1) * 8;
    const uint32_t kA = (uint32_t)(grp >> 1) * 16;
    const uint32_t kB = (uint32_t)(grp & 1) * 16;

    float acc[2][8][4];
    #pragma unroll
    for (int mt = 0; mt < 2; mt++)
        #pragma unroll
        for (int nt = 0; nt < 8; nt++)
            #pragma unroll
            for (int j = 0; j < 4; j++) acc[mt][nt][j] = 0.f;

    // ---- stage loader ----
    auto load_stage = [&](int kb, int st) {
        int seg = kb >> cpsLog;
        int koff = (kb & ((1 << cpsLog) - 1)) << 6;
        const __nv_bfloat16* Aseg = segs.A[seg];
        const __nv_bfloat16* Wseg = segs.W[seg];
        uint32_t sA = sb + (uint32_t)st * 32768u;
        uint32_t sB = sA + 16384u;
        #pragma unroll
        for (int t = 0; t < 4; t++) {
            int idx = tid + t * 256;
            int row = idx >> 3, ch = idx & 7;
            uint32_t swz = (uint32_t)row * 128u + (((uint32_t)ch * 16u) ^ (((uint32_t)row & 7u) << 4));
            int grow = bm0 + row;
            int ok = grow < N_NODES;
            const void* gA = Aseg + (size_t)(ok ? grow : 0) * D + koff + ch * 8;
            int sz = ok ? 16 : 0;
            asm volatile("cp.async.cg.shared.global [%0], [%1], 16, %2;"
                         :: "r"(sA + swz), "l"(gA), "r"(sz));
            const void* gB = Wseg + (size_t)(bn0 + row) * D + koff + ch * 8;
            asm volatile("cp.async.cg.shared.global [%0], [%1], 16;"
                         :: "r"(sB + swz), "l"(gB));
        }
        asm volatile("cp.async.commit_group;");
    };

    // ---- compute one 64-wide K stage ----
    auto compute_stage = [&](int st) {
        uint32_t aBase = sb + (uint32_t)st * 32768u + (uint32_t)rowA0 * 128u;
        uint32_t bBase = sb + (uint32_t)st * 32768u + 16384u + (uint32_t)rowB0 * 128u;
        #pragma unroll
        for (int kt = 0; kt < 4; kt++) {
            uint32_t a[2][4];
            #pragma unroll
            for (int mt = 0; mt < 2; mt++) {
                uint32_t ad = aBase + (uint32_t)mt * 2048u + (((uint32_t)kt * 32u + kA) ^ xr);
                asm volatile("ldmatrix.sync.aligned.m8n8.x4.shared.b16 {%0,%1,%2,%3}, [%4];"
                    : "=r"(a[mt][0]), "=r"(a[mt][1]), "=r"(a[mt][2]), "=r"(a[mt][3]) : "r"(ad));
            }
            #pragma unroll
            for (int np = 0; np < 4; np++) {
                uint32_t b0, b1, b2, b3;
                uint32_t bd = bBase + (uint32_t)np * 2048u + (((uint32_t)kt * 32u + kB) ^ xr);
                asm volatile("ldmatrix.sync.aligned.m8n8.x4.shared.b16 {%0,%1,%2,%3}, [%4];"
                    : "=r"(b0), "=r"(b1), "=r"(b2), "=r"(b3) : "r"(bd));
                #pragma unroll
                for (int mt = 0; mt < 2; mt++) {
                    MMA_BF16(acc[mt][np * 2 + 0], a[mt], b0, b1);
                    MMA_BF16(acc[mt][np * 2 + 1], a[mt], b2, b3);
                }
            }
        }
    };

    // ---- pipelined main loop ----
    load_stage(0, 0);
    for (int kb = 0; kb < nkb; kb++) {
        bool more = (kb + 1) < nkb;
        if (more) load_stage(kb + 1, (kb + 1) & 1);
        if (more) asm volatile("cp.async.wait_group 1;");
        else      asm volatile("cp.async.wait_group 0;");
        __syncthreads();
        compute_stage(kb & 1);
        __syncthreads();
    }

    // ---- epilogue ----
    int r0 = bm0 + wm * 32 + (lane >> 2);
    int cb = bn0 + wn * 64 + (lane & 3) * 2;
    #pragma unroll
    for (int mt = 0; mt < 2; mt++) {
        #pragma unroll
        for (int nt = 0; nt < 8; nt++) {
            int row = r0 + mt * 16;
            int col = cb + nt * 8;
            float bv0 = __ldg(&bias[col]), bv1 = __ldg(&bias[col + 1]);
            float h0 = acc[mt][nt][0] + bv0, h1 = acc[mt][nt][1] + bv1;
            float h2 = acc[mt][nt][2] + bv0, h3 = acc[mt][nt][3] + bv1;
            if (relu) {
                h0 = fmaxf(h0, 0.f); h1 = fmaxf(h1, 0.f);
                h2 = fmaxf(h2, 0.f); h3 = fmaxf(h3, 0.f);
            }
            if (row < N_NODES)     *(float2*)(C + (size_t)row * NT + col)       = make_float2(h0, h1);
            if (row + 8 < N_NODES) *(float2*)(C + (size_t)(row + 8) * NT + col) = make_float2(h2, h3);
        }
    }
}

// ======================= BN column stats over h_raw =======================
__global__ void k_colstats(const float* __restrict__ h) {
    int t = threadIdx.x;                  // column 0..255
    int r0 = blockIdx.x * 256;
    float s = 0.f, q = 0.f;
    #pragma unroll 4
    for (int r = 0; r < 256; r++) {
        int row = r0 + r;
        if (row < N_NODES) {
            float v = h[(size_t)row * HID + t];
            s += v; q += v * v;
        }
    }
    atomicAdd(&g_colsum[t], s);
    atomicAdd(&g_colsumsq[t], q);
}

__global__ void k_stats(const float* __restrict__ g, const float* __restrict__ be) {
    int j = threadIdx.x;
    if (j < HID) {
        float mu  = g_colsum[j] / (float)N_NODES;
        float var = g_colsumsq[j] / (float)N_NODES - mu * mu;
        var = fmaxf(var, 0.f);
        float a = g[j] * rsqrtf(var + EPS);
        g_na[j] = a;
        g_nc[j] = be[j] - mu * a;
        g_colsum[j] = 0.f;
        g_colsumsq[j] = 0.f;
    }
}

// normalize + relu + hi/lo bf16 split
__global__ void k_normfuse(const float* __restrict__ h,
                           __nv_bfloat16* __restrict__ oh, __nv_bfloat16* __restrict__ ol) {
    int i = blockIdx.x * blockDim.x + threadIdx.x;   // float4 index
    if (i >= N_NODES * HID / 4) return;
    float4 v = ((const float4*)h)[i];
    int cidx = (i * 4) & (HID - 1);
    v.x = fmaxf(v.x * g_na[cidx + 0] + g_nc[cidx + 0], 0.f);
    v.y = fmaxf(v.y * g_na[cidx + 1] + g_nc[cidx + 1], 0.f);
    v.z = fmaxf(v.z * g_na[cidx + 2] + g_nc[cidx + 2], 0.f);
    v.w = fmaxf(v.w * g_na[cidx + 3] + g_nc[cidx + 3], 0.f);
    uint2 uh, ul;
    uh.x = pack2bf(v.x, v.y); uh.y = pack2bf(v.z, v.w);
    ul.x = pack2bf(lo_of(v.x), lo_of(v.y)); ul.y = pack2bf(lo_of(v.z), lo_of(v.w));
    ((uint2*)oh)[i] = uh;
    ((uint2*)ol)[i] = ul;
}

// ======================= final GEMV =======================
__global__ void k_final(const float* __restrict__ z, const float* __restrict__ cw2,
                        const float* __restrict__ cb2, float* __restrict__ out) {
    int w = (blockIdx.x * blockDim.x + threadIdx.x) >> 5;
    int lane = threadIdx.x & 31;
    if (w >= N_NODES) return;
    float4 v = ((const float4*)(z + (size_t)w * 128))[lane];
    int k = lane * 4;
    float o0 = v.x * cw2[(k + 0) * 2 + 0] + v.y * cw2[(k + 1) * 2 + 0]
             + v.z * cw2[(k + 2) * 2 + 0] + v.w * cw2[(k + 3) * 2 + 0];
    float o1 = v.x * cw2[(k + 0) * 2 + 1] + v.y * cw2[(k + 1) * 2 + 1]
             + v.z * cw2[(k + 2) * 2 + 1] + v.w * cw2[(k + 3) * 2 + 1];
    #pragma unroll
    for (int off = 16; off; off >>= 1) {
        o0 += __shfl_down_sync(0xffffffffu, o0, off);
        o1 += __shfl_down_sync(0xffffffffu, o1, off);
    }
    if (lane == 0) {
        out[2 * w + 0] = o0 + cb2[0];
        out[2 * w + 1] = o1 + cb2[1];
    }
}

// ======================= launch =======================
extern "C" void kernel_launch(void* const* d_in, const int* in_sizes, int n_in,
                              void* d_out, int out_size) {
    const float* x    = (const float*)d_in[0];
    const int*   ei   = (const int*)d_in[1];   // int32 (JAX x64 disabled)
    const int*   srcv = ei;
    const int*   dstv = ei + N_EDGES;
    const float* wl0 = (const float*)d_in[2];
    const float* wr0 = (const float*)d_in[3];
    const float* b0  = (const float*)d_in[4];
    const float* g0  = (const float*)d_in[5];
    const float* be0 = (const float*)d_in[6];
    const float* wl1 = (const float*)d_in[7];
    const float* wr1 = (const float*)d_in[8];
    const float* b1  = (const float*)d_in[9];
    const float* g1  = (const float*)d_in[10];
    const float* be1 = (const float*)d_in[11];
    const float* wl2 = (const float*)d_in[12];
    const float* wr2 = (const float*)d_in[13];
    const float* b2  = (const float*)d_in[14];
    const float* g2  = (const float*)d_in[15];
    const float* be2 = (const float*)d_in[16];
    const float* cw1 = (const float*)d_in[17];
    const float* cb1 = (const float*)d_in[18];
    const float* cw2 = (const float*)d_in[19];
    const float* cb2 = (const float*)d_in[20];
    float* out = (float*)d_out;

    float* hraw;
    __nv_bfloat16 *ah, *al, *bh1, *bl1, *bh2, *bl2, *wp;
    cudaGetSymbolAddress((void**)&hraw, g_hraw);
    cudaGetSymbolAddress((void**)&ah, g_ah);
    cudaGetSymbolAddress((void**)&al, g_al);
    cudaGetSymbolAddress((void**)&bh1, g_bh1);
    cudaGetSymbolAddress((void**)&bl1, g_bl1);
    cudaGetSymbolAddress((void**)&bh2, g_bh2);
    cudaGetSymbolAddress((void**)&bl2, g_bl2);
    cudaGetSymbolAddress((void**)&wp, g_w);

    const int SMEM = 65536;
    cudaFuncSetAttribute(k_mma<256>, cudaFuncAttributeMaxDynamicSharedMemorySize, SMEM);
    cudaFuncSetAttribute(k_mma<128>, cudaFuncAttributeMaxDynamicSharedMemorySize, SMEM);

    // ---- CSR build ----
    k_init<<<(N_NODES + 255) / 256, 256>>>();
    k_hist<<<(N_EDGES + 255) / 256, 256>>>(dstv);
    int nb = (N_NODES + 1023) / 1024;
    k_scan1<<<nb, 1024>>>();
    k_scan2<<<1, 32>>>(nb);
    k_scan3<<<nb, 1024>>>();
    k_fill<<<(N_EDGES + 255) / 256, 256>>>(srcv, dstv);

    // ---- weight + x conversion ----
    int wg128 = (128 * 256 + 255) / 256, wg256 = (256 * 256 + 255) / 256, wgc = (256 * 128 + 255) / 256;
    k_convw<<<wg128, 256>>>(wl0, wp + WL0H, wp + WL0L, 128, 256);
    k_convw<<<wg128, 256>>>(wr0, wp + WR0H, wp + WR0L, 128, 256);
    k_convw<<<wg256, 256>>>(wl1, wp + WL1H, wp + WL1L, 256, 256);
    k_convw<<<wg256, 256>>>(wr1, wp + WR1H, wp + WR1L, 256, 256);
    k_convw<<<wg256, 256>>>(wl2, wp + WL2H, wp + WL2L, 256, 256);
    k_convw<<<wg256, 256>>>(wr2, wp + WR2H, wp + WR2L, 256, 256);
    k_convw<<<wgc, 256>>>(cw1, wp + CW1H, wp + CW1L, 256, 128);
    k_convx<<<(N_NODES * IN_DIM / 4 + 255) / 256, 256>>>(x, bh2, bl2);

    int aggGrid = (N_NODES * 32 + 255) / 256;
    int nfGrid  = (N_NODES * HID / 4 + 255) / 256;
    int csGrid  = (N_NODES + 255) / 256;
    int mblocks = (N_NODES + 127) / 128;          // 782
    dim3 gMain(2, mblocks);                       // NT=256
    dim3 gCls(1, mblocks);                        // NT=128

    // ---- layer 0 (D=128): A2 = x (bh2/bl2) ----
    k_agg_f32<<<aggGrid, 256>>>(x, ah, al);
    {
        GemmSegs s;
        s.A[0] = ah;  s.W[0] = wp + WL0H;
        s.A[1] = ah;  s.W[1] = wp + WL0L;
        s.A[2] = al;  s.W[2] = wp + WL0H;
        s.A[3] = bh2; s.W[3] = wp + WR0H;
        s.A[4] = bh2; s.W[4] = wp + WR0L;
        s.A[5] = bl2; s.W[5] = wp + WR0H;
        k_mma<256><<<gMain, 256, SMEM>>>(s, 6, 128, b0, hraw, 0);
    }
    k_colstats<<<csGrid, 256>>>(hraw);
    k_stats<<<1, 256>>>(g0, be0);
    k_normfuse<<<nfGrid, 256>>>(hraw, bh1, bl1);

    // ---- layer 1 (D=256) ----
    k_agg_bf16<<<aggGrid, 256>>>(bh1, bl1, ah, al);
    {
        GemmSegs s;
        s.A[0] = ah;  s.W[0] = wp + WL1H;
        s.A[1] = ah;  s.W[1] = wp + WL1L;
        s.A[2] = al;  s.W[2] = wp + WL1H;
        s.A[3] = bh1; s.W[3] = wp + WR1H;
        s.A[4] = bh1; s.W[4] = wp + WR1L;
        s.A[5] = bl1; s.W[5] = wp + WR1H;
        k_mma<256><<<gMain, 256, SMEM>>>(s, 6, 256, b1, hraw, 0);
    }
    k_colstats<<<csGrid, 256>>>(hraw);
    k_stats<<<1, 256>>>(g1, be1);
    k_normfuse<<<nfGrid, 256>>>(hraw, bh2, bl2);

    // ---- layer 2 (D=256) ----
    k_agg_bf16<<<aggGrid, 256>>>(bh2, bl2, ah, al);
    {
        GemmSegs s;
        s.A[0] = ah;  s.W[0] = wp + WL2H;
        s.A[1] = ah;  s.W[1] = wp + WL2L;
        s.A[2] = al;  s.W[2] = wp + WL2H;
        s.A[3] = bh2; s.W[3] = wp + WR2H;
        s.A[4] = bh2; s.W[4] = wp + WR2L;
        s.A[5] = bl2; s.W[5] = wp + WR2H;
        k_mma<256><<<gMain, 256, SMEM>>>(s, 6, 256, b2, hraw, 0);
    }
    k_colstats<<<csGrid, 256>>>(hraw);
    k_stats<<<1, 256>>>(g2, be2);
    k_normfuse<<<nfGrid, 256>>>(hraw, bh1, bl1);

    // ---- classifier: z = relu(h2 @ cw1 + cb1) -> hraw [N,128] ----
    {
        GemmSegs s;
        s.A[0] = bh1; s.W[0] = wp + CW1H;
        s.A[1] = bh1; s.W[1] = wp + CW1L;
        s.A[2] = bl1; s.W[2] = wp + CW1H;
        s.A[3] = nullptr; s.W[3] = nullptr;
        s.A[4] = nullptr; s.W[4] = nullptr;
        s.A[5] = nullptr; s.W[5] = nullptr;
        k_mma<128><<<gCls, 256, SMEM>>>(s, 3, 256, cb1, hraw, 1);
    }
    k_final<<<aggGrid, 256>>>(hraw, cw2, cb2, out);
}

// round 5
// speedup vs baseline: 2.1068x; 1.0844x over previous
#include <cuda_runtime.h>
#include <cuda_bf16.h>
#include <cstdint>

#define N_NODES 100000
#define N_EDGES 1600000
#define IN_DIM 128
#define HID 256
#define EPS 1e-5f

// ======================= scratch (static __device__) =======================
__device__ float g_hraw[N_NODES * HID];                 // GEMM output fp32
__device__ __nv_bfloat16 g_ah[N_NODES * HID];           // agg hi
__device__ __nv_bfloat16 g_al[N_NODES * HID];           // agg lo
__device__ __nv_bfloat16 g_bh1[N_NODES * HID];          // buf A hi
__device__ __nv_bfloat16 g_bl1[N_NODES * HID];          // buf A lo
__device__ __nv_bfloat16 g_bh2[N_NODES * HID];          // buf B hi
__device__ __nv_bfloat16 g_bl2[N_NODES * HID];          // buf B lo
__device__ __nv_bfloat16 g_w[720896];                   // converted weights W^T [N][K] hi/lo
__device__ int   g_cnt[N_NODES];
__device__ int   g_cursor[N_NODES];
__device__ int   g_scantmp[N_NODES];
__device__ int   g_rowptr[N_NODES + 1];
__device__ int   g_adj[N_EDGES];
__device__ int   g_bsum[128];
__device__ float g_colsum[HID];
__device__ float g_colsumsq[HID];
__device__ float g_na[HID];
__device__ float g_nc[HID];

// weight pool offsets (elements)
#define WL0H 0
#define WL0L 32768
#define WR0H 65536
#define WR0L 98304
#define WL1H 131072
#define WL1L 196608
#define WR1H 262144
#define WR1L 327680
#define WL2H 393216
#define WL2L 458752
#define WR2H 524288
#define WR2L 589824
#define CW1H 655360
#define CW1L 688128

__device__ __forceinline__ uint32_t smem_u32(const void* p) {
    uint32_t a;
    asm("{ .reg .u64 t; cvta.to.shared.u64 t, %1; cvt.u32.u64 %0, t; }" : "=r"(a) : "l"(p));
    return a;
}

// ======================= CSR build =======================
__global__ void k_init() {
    int i = blockIdx.x * blockDim.x + threadIdx.x;
    if (i < N_NODES) { g_cnt[i] = 0; g_cursor[i] = 0; }
    if (i < HID)     { g_colsum[i] = 0.f; g_colsumsq[i] = 0.f; }
}
__global__ void k_hist(const int* __restrict__ dst) {
    int e = blockIdx.x * blockDim.x + threadIdx.x;
    if (e < N_EDGES) atomicAdd(&g_cnt[dst[e]], 1);
}
__global__ void k_scan1() {
    __shared__ int s[1024];
    int i = blockIdx.x * 1024 + threadIdx.x;
    int v = (i < N_NODES) ? g_cnt[i] : 0;
    s[threadIdx.x] = v;
    __syncthreads();
    #pragma unroll
    for (int off = 1; off < 1024; off <<= 1) {
        int t = (threadIdx.x >= off) ? s[threadIdx.x - off] : 0;
        __syncthreads();
        s[threadIdx.x] += t;
        __syncthreads();
    }
    if (i < N_NODES) g_scantmp[i] = s[threadIdx.x];
    if (threadIdx.x == 1023) g_bsum[blockIdx.x] = s[1023];
}
__global__ void k_scan2(int nb) {
    if (threadIdx.x == 0 && blockIdx.x == 0) {
        int acc = 0;
        for (int i = 0; i < nb; i++) { int v = g_bsum[i]; g_bsum[i] = acc; acc += v; }
    }
}
__global__ void k_scan3() {
    int i = blockIdx.x * 1024 + threadIdx.x;
    if (i < N_NODES) {
        g_rowptr[i + 1] = g_scantmp[i] + g_bsum[blockIdx.x];
        if (i == 0) g_rowptr[0] = 0;
    }
}
__global__ void k_fill(const int* __restrict__ src, const int* __restrict__ dst) {
    int e = blockIdx.x * blockDim.x + threadIdx.x;
    if (e < N_EDGES) {
        int d = dst[e];
        int pos = g_rowptr[d] + atomicAdd(&g_cursor[d], 1);
        g_adj[pos] = src[e];
    }
}

// ======================= bf16 pack helpers =======================
__device__ __forceinline__ uint32_t pack2bf(float a, float b) {
    uint16_t ua = __bfloat16_as_ushort(__float2bfloat16(a));
    uint16_t ub = __bfloat16_as_ushort(__float2bfloat16(b));
    return (uint32_t)ua | ((uint32_t)ub << 16);
}
__device__ __forceinline__ float lo_of(float v) {
    return v - __bfloat162float(__float2bfloat16(v));
}

// ======================= aggregation =======================
__global__ void k_agg_f32(const float* __restrict__ x,
                          __nv_bfloat16* __restrict__ oh, __nv_bfloat16* __restrict__ ol) {
    int w = (blockIdx.x * blockDim.x + threadIdx.x) >> 5;
    int lane = threadIdx.x & 31;
    if (w >= N_NODES) return;
    int s0 = g_rowptr[w], s1 = g_rowptr[w + 1];
    float4 a0 = make_float4(0.f, 0.f, 0.f, 0.f);
    for (int e = s0; e < s1; e++) {
        const float4* p = (const float4*)(x + (size_t)g_adj[e] * IN_DIM);
        float4 v = p[lane];
        a0.x += v.x; a0.y += v.y; a0.z += v.z; a0.w += v.w;
    }
    int deg = s1 - s0;
    float inv = 1.f / (float)(deg > 0 ? deg : 1);
    a0.x *= inv; a0.y *= inv; a0.z *= inv; a0.w *= inv;
    size_t base = (size_t)w * IN_DIM + lane * 4;
    uint2 uh, ul;
    uh.x = pack2bf(a0.x, a0.y); uh.y = pack2bf(a0.z, a0.w);
    ul.x = pack2bf(lo_of(a0.x), lo_of(a0.y)); ul.y = pack2bf(lo_of(a0.z), lo_of(a0.w));
    *(uint2*)(oh + base) = uh;
    *(uint2*)(ol + base) = ul;
}

__global__ void k_agg_bf16(const __nv_bfloat16* __restrict__ xh, const __nv_bfloat16* __restrict__ xl,
                           __nv_bfloat16* __restrict__ oh, __nv_bfloat16* __restrict__ ol) {
    int w = (blockIdx.x * blockDim.x + threadIdx.x) >> 5;
    int lane = threadIdx.x & 31;
    if (w >= N_NODES) return;
    int s0 = g_rowptr[w], s1 = g_rowptr[w + 1];
    float acc[8];
    #pragma unroll
    for (int i = 0; i < 8; i++) acc[i] = 0.f;
    for (int e = s0; e < s1; e++) {
        size_t base = (size_t)g_adj[e] * HID + lane * 8;
        uint4 vh = *(const uint4*)(xh + base);
        uint4 vl = *(const uint4*)(xl + base);
        const uint32_t* ph = &vh.x;
        const uint32_t* pl = &vl.x;
        #pragma unroll
        for (int i = 0; i < 4; i++) {
            float2 fh = __bfloat1622float2(*(const __nv_bfloat162*)&ph[i]);
            float2 fl = __bfloat1622float2(*(const __nv_bfloat162*)&pl[i]);
            acc[i * 2 + 0] += fh.x + fl.x;
            acc[i * 2 + 1] += fh.y + fl.y;
        }
    }
    int deg = s1 - s0;
    float inv = 1.f / (float)(deg > 0 ? deg : 1);
    uint4 uh, ul;
    uint32_t* ph = &uh.x; uint32_t* pl = &ul.x;
    #pragma unroll
    for (int i = 0; i < 4; i++) {
        float v0 = acc[i * 2] * inv, v1 = acc[i * 2 + 1] * inv;
        ph[i] = pack2bf(v0, v1);
        pl[i] = pack2bf(lo_of(v0), lo_of(v1));
    }
    size_t base = (size_t)w * HID + lane * 8;
    *(uint4*)(oh + base) = uh;
    *(uint4*)(ol + base) = ul;
}

// ======================= conversions =======================
__global__ void k_convx(const float* __restrict__ x,
                        __nv_bfloat16* __restrict__ oh, __nv_bfloat16* __restrict__ ol) {
    int i = blockIdx.x * blockDim.x + threadIdx.x;   // float4 index
    if (i >= N_NODES * IN_DIM / 4) return;
    float4 v = ((const float4*)x)[i];
    uint2 uh, ul;
    uh.x = pack2bf(v.x, v.y); uh.y = pack2bf(v.z, v.w);
    ul.x = pack2bf(lo_of(v.x), lo_of(v.y)); ul.y = pack2bf(lo_of(v.z), lo_of(v.w));
    ((uint2*)oh)[i] = uh;
    ((uint2*)ol)[i] = ul;
}

// All weights: fp32 [K,N] -> W^T bf16 [N][K] hi/lo, 7 jobs in one launch
struct ConvJobs { const float* W[7]; int K[7]; int N[7]; int oh[7]; int ol[7]; };
__global__ void k_convall(ConvJobs j, __nv_bfloat16* __restrict__ wp) {
    int s = blockIdx.y;
    int K = j.K[s], N = j.N[s];
    int id = blockIdx.x * blockDim.x + threadIdx.x;
    if (id >= K * N) return;
    int k = id / N, n = id % N;
    float v = __ldg(&j.W[s][id]);
    size_t pos = (size_t)n * K + k;
    wp[j.oh[s] + pos] = __float2bfloat16(v);
    wp[j.ol[s] + pos] = __float2bfloat16(lo_of(v));
}

// ======================= bf16 mma.sync GEMM =======================
// STATS: accumulate BN column sum/sumsq into g_colsum/g_colsumsq
// FINAL: skip C tile store; C = out[N,2]; fuse out = relu(z) @ w2 + b2
struct GemmSegs { const __nv_bfloat16* A[6]; const __nv_bfloat16* W[6]; };

#define MMA_BF16(c, a, b0v, b1v) \
    asm volatile("mma.sync.aligned.m16n8k16.row.col.f32.bf16.bf16.f32 " \
        "{%0,%1,%2,%3}, {%4,%5,%6,%7}, {%8,%9}, {%0,%1,%2,%3};" \
        : "+f"((c)[0]), "+f"((c)[1]), "+f"((c)[2]), "+f"((c)[3]) \
        : "r"((a)[0]), "r"((a)[1]), "r"((a)[2]), "r"((a)[3]), "r"(b0v), "r"(b1v))

template <int NT, int STATS, int FINAL>
__global__ __launch_bounds__(256, 2)
void k_mma(GemmSegs segs, int nseg, int D, const float* __restrict__ bias,
           float* __restrict__ C, int relu,
           const float* __restrict__ w2, const float* __restrict__ b2) {
    extern __shared__ char dsm[];                 // 3 stages x [A 16KB | B 16KB]
    __shared__ float scol[128], scolq[128];
    __shared__ float srow[256];
    __shared__ float s_w2[256];
    const uint32_t sb = smem_u32(dsm);
    const int tid = threadIdx.x;
    const int lane = tid & 31, wid = tid >> 5;
    const int wm = wid & 3, wn = wid >> 2;        // 4 m-warps x 2 n-warps
    const int bm0 = blockIdx.y * 128, bn0 = blockIdx.x * 128;
    const int grp = lane >> 3, tg = lane & 7;

    if (STATS && tid < 128) { scol[tid] = 0.f; scolq[tid] = 0.f; }
    if (FINAL && tid < 256) { srow[tid] = 0.f; s_w2[tid] = __ldg(&w2[tid]); }

    const int cpsLog = (D == 256) ? 2 : 1;        // k64-blocks per segment (log2)
    const int nkb = nseg << cpsLog;

    // ldmatrix per-thread geometry (XOR-swizzled 128B rows)
    const uint32_t xr = (uint32_t)tg << 4;
    const int rowA0 = wm * 32 + tg + (grp & 1) * 8;
    const int rowB0 = wn * 64 + tg + (grp >> 1) * 8;
    const uint32_t kA = (uint32_t)(grp >> 1) * 16;
    const uint32_t kB = (uint32_t)(grp & 1) * 16;

    float acc[2][8][4];
    #pragma unroll
    for (int mt = 0; mt < 2; mt++)
        #pragma unroll
        for (int nt = 0; nt < 8; nt++)
            #pragma unroll
            for (int j = 0; j < 4; j++) acc[mt][nt][j] = 0.f;

    // ---- stage loader (one commit group per call) ----
    auto load_stage = [&](int kb, int st) {
        int seg = kb >> cpsLog;
        int koff = (kb & ((1 << cpsLog) - 1)) << 6;
        const __nv_bfloat16* Aseg = segs.A[seg];
        const __nv_bfloat16* Wseg = segs.W[seg];
        uint32_t sA = sb + (uint32_t)st * 32768u;
        uint32_t sB = sA + 16384u;
        #pragma unroll
        for (int t = 0; t < 4; t++) {
            int idx = tid + t * 256;
            int row = idx >> 3, ch = idx & 7;
            uint32_t swz = (uint32_t)row * 128u + (((uint32_t)ch * 16u) ^ (((uint32_t)row & 7u) << 4));
            int grow = bm0 + row;
            int ok = grow < N_NODES;
            const void* gA = Aseg + (size_t)(ok ? grow : 0) * D + koff + ch * 8;
            int sz = ok ? 16 : 0;
            asm volatile("cp.async.cg.shared.global [%0], [%1], 16, %2;"
                         :: "r"(sA + swz), "l"(gA), "r"(sz));
            const void* gB = Wseg + (size_t)(bn0 + row) * D + koff + ch * 8;
            asm volatile("cp.async.cg.shared.global [%0], [%1], 16;"
                         :: "r"(sB + swz), "l"(gB));
        }
        asm volatile("cp.async.commit_group;");
    };

    // ---- compute one 64-wide K stage ----
    auto compute_stage = [&](int st) {
        uint32_t aBase = sb + (uint32_t)st * 32768u + (uint32_t)rowA0 * 128u;
        uint32_t bBase = sb + (uint32_t)st * 32768u + 16384u + (uint32_t)rowB0 * 128u;
        #pragma unroll
        for (int kt = 0; kt < 4; kt++) {
            uint32_t a[2][4];
            #pragma unroll
            for (int mt = 0; mt < 2; mt++) {
                uint32_t ad = aBase + (uint32_t)mt * 2048u + (((uint32_t)kt * 32u + kA) ^ xr);
                asm volatile("ldmatrix.sync.aligned.m8n8.x4.shared.b16 {%0,%1,%2,%3}, [%4];"
                    : "=r"(a[mt][0]), "=r"(a[mt][1]), "=r"(a[mt][2]), "=r"(a[mt][3]) : "r"(ad));
            }
            #pragma unroll
            for (int np = 0; np < 4; np++) {
                uint32_t b0, b1, b2r, b3;
                uint32_t bd = bBase + (uint32_t)np * 2048u + (((uint32_t)kt * 32u + kB) ^ xr);
                asm volatile("ldmatrix.sync.aligned.m8n8.x4.shared.b16 {%0,%1,%2,%3}, [%4];"
                    : "=r"(b0), "=r"(b1), "=r"(b2r), "=r"(b3) : "r"(bd));
                #pragma unroll
                for (int mt = 0; mt < 2; mt++) {
                    MMA_BF16(acc[mt][np * 2 + 0], a[mt], b0, b1);
                    MMA_BF16(acc[mt][np * 2 + 1], a[mt], b2r, b3);
                }
            }
        }
    };

    // ---- 3-stage pipelined main loop (single sync per iter) ----
    load_stage(0, 0);
    load_stage(1, 1);
    int st = 0;
    for (int kb = 0; kb < nkb; kb++) {
        if (kb < nkb - 1) asm volatile("cp.async.wait_group 1;");
        else              asm volatile("cp.async.wait_group 0;");
        __syncthreads();
        compute_stage(st);
        if (kb + 2 < nkb) {
            int st2 = st + 2; if (st2 >= 3) st2 -= 3;
            load_stage(kb + 2, st2);
        }
        if (++st == 3) st = 0;
    }

    // ---- epilogue ----
    const int rbase = wm * 32 + (lane >> 2);
    const int cbL = wn * 64 + (lane & 3) * 2;     // local col
    float po[8];
    #pragma unroll
    for (int i = 0; i < 8; i++) po[i] = 0.f;

    #pragma unroll
    for (int nt = 0; nt < 8; nt++) {
        int colL = cbL + nt * 8;
        int col = bn0 + colL;
        float bv0 = __ldg(&bias[col]), bv1 = __ldg(&bias[col + 1]);
        float s0 = 0.f, s1 = 0.f, q0 = 0.f, q1 = 0.f;
        #pragma unroll
        for (int mt = 0; mt < 2; mt++) {
            int row = bm0 + rbase + mt * 16;
            float h0 = acc[mt][nt][0] + bv0, h1 = acc[mt][nt][1] + bv1;
            float h2 = acc[mt][nt][2] + bv0, h3 = acc[mt][nt][3] + bv1;
            if (relu) {
                h0 = fmaxf(h0, 0.f); h1 = fmaxf(h1, 0.f);
                h2 = fmaxf(h2, 0.f); h3 = fmaxf(h3, 0.f);
            }
            bool v0 = row < N_NODES, v1 = (row + 8) < N_NODES;
            if (STATS) {
                float a0 = v0 ? h0 : 0.f, a1 = v0 ? h1 : 0.f;
                float a2 = v1 ? h2 : 0.f, a3 = v1 ? h3 : 0.f;
                s0 += a0 + a2; s1 += a1 + a3;
                q0 += a0 * a0 + a2 * a2; q1 += a1 * a1 + a3 * a3;
            }
            if (!FINAL) {
                if (v0) *(float2*)(C + (size_t)row * NT + col) = make_float2(h0, h1);
                if (v1) *(float2*)(C + (size_t)(row + 8) * NT + col) = make_float2(h2, h3);
            } else {
                float w20 = s_w2[colL * 2], w21 = s_w2[colL * 2 + 1];
                float w30 = s_w2[(colL + 1) * 2], w31 = s_w2[(colL + 1) * 2 + 1];
                po[mt * 4 + 0] += h0 * w20 + h1 * w30;
                po[mt * 4 + 1] += h0 * w21 + h1 * w31;
                po[mt * 4 + 2] += h2 * w20 + h3 * w30;
                po[mt * 4 + 3] += h2 * w21 + h3 * w31;
            }
        }
        if (STATS) {
            #pragma unroll
            for (int off = 4; off <= 16; off <<= 1) {
                s0 += __shfl_xor_sync(0xffffffffu, s0, off);
                s1 += __shfl_xor_sync(0xffffffffu, s1, off);
                q0 += __shfl_xor_sync(0xffffffffu, q0, off);
                q1 += __shfl_xor_sync(0xffffffffu, q1, off);
            }
            if ((lane >> 2) == 0) {
                atomicAdd(&scol[colL], s0);  atomicAdd(&scol[colL + 1], s1);
                atomicAdd(&scolq[colL], q0); atomicAdd(&scolq[colL + 1], q1);
            }
        }
    }
    if (STATS) {
        __syncthreads();
        if (tid < 128) {
            atomicAdd(&g_colsum[bn0 + tid], scol[tid]);
            atomicAdd(&g_colsumsq[bn0 + tid], scolq[tid]);
        }
    }
    if (FINAL) {
        #pragma unroll
        for (int mt = 0; mt < 2; mt++) {
            int rl = rbase + mt * 16;
            atomicAdd(&srow[rl * 2 + 0], po[mt * 4 + 0]);
            atomicAdd(&srow[rl * 2 + 1], po[mt * 4 + 1]);
            atomicAdd(&srow[(rl + 8) * 2 + 0], po[mt * 4 + 2]);
            atomicAdd(&srow[(rl + 8) * 2 + 1], po[mt * 4 + 3]);
        }
        __syncthreads();
        if (tid < 128) {
            int grow = bm0 + tid;
            if (grow < N_NODES) {
                C[(size_t)grow * 2 + 0] = srow[tid * 2 + 0] + __ldg(&b2[0]);
                C[(size_t)grow * 2 + 1] = srow[tid * 2 + 1] + __ldg(&b2[1]);
            }
        }
    }
}

// ======================= BN stats -> affine =======================
__global__ void k_stats(const float* __restrict__ g, const float* __restrict__ be) {
    int j = threadIdx.x;
    if (j < HID) {
        float mu  = g_colsum[j] / (float)N_NODES;
        float var = g_colsumsq[j] / (float)N_NODES - mu * mu;
        var = fmaxf(var, 0.f);
        float a = g[j] * rsqrtf(var + EPS);
        g_na[j] = a;
        g_nc[j] = be[j] - mu * a;
        g_colsum[j] = 0.f;
        g_colsumsq[j] = 0.f;
    }
}

// normalize + relu + hi/lo bf16 split
__global__ void k_normfuse(const float* __restrict__ h,
                           __nv_bfloat16* __restrict__ oh, __nv_bfloat16* __restrict__ ol) {
    int i = blockIdx.x * blockDim.x + threadIdx.x;   // float4 index
    if (i >= N_NODES * HID / 4) return;
    float4 v = ((const float4*)h)[i];
    int cidx = (i * 4) & (HID - 1);
    v.x = fmaxf(v.x * g_na[cidx + 0] + g_nc[cidx + 0], 0.f);
    v.y = fmaxf(v.y * g_na[cidx + 1] + g_nc[cidx + 1], 0.f);
    v.z = fmaxf(v.z * g_na[cidx + 2] + g_nc[cidx + 2], 0.f);
    v.w = fmaxf(v.w * g_na[cidx + 3] + g_nc[cidx + 3], 0.f);
    uint2 uh, ul;
    uh.x = pack2bf(v.x, v.y); uh.y = pack2bf(v.z, v.w);
    ul.x = pack2bf(lo_of(v.x), lo_of(v.y)); ul.y = pack2bf(lo_of(v.z), lo_of(v.w));
    ((uint2*)oh)[i] = uh;
    ((uint2*)ol)[i] = ul;
}

// ======================= launch =======================
extern "C" void kernel_launch(void* const* d_in, const int* in_sizes, int n_in,
                              void* d_out, int out_size) {
    const float* x    = (const float*)d_in[0];
    const int*   ei   = (const int*)d_in[1];   // int32 (JAX x64 disabled)
    const int*   srcv = ei;
    const int*   dstv = ei + N_EDGES;
    const float* wl0 = (const float*)d_in[2];
    const float* wr0 = (const float*)d_in[3];
    const float* b0  = (const float*)d_in[4];
    const float* g0  = (const float*)d_in[5];
    const float* be0 = (const float*)d_in[6];
    const float* wl1 = (const float*)d_in[7];
    const float* wr1 = (const float*)d_in[8];
    const float* b1  = (const float*)d_in[9];
    const float* g1  = (const float*)d_in[10];
    const float* be1 = (const float*)d_in[11];
    const float* wl2 = (const float*)d_in[12];
    const float* wr2 = (const float*)d_in[13];
    const float* b2  = (const float*)d_in[14];
    const float* g2  = (const float*)d_in[15];
    const float* be2 = (const float*)d_in[16];
    const float* cw1 = (const float*)d_in[17];
    const float* cb1 = (const float*)d_in[18];
    const float* cw2 = (const float*)d_in[19];
    const float* cb2 = (const float*)d_in[20];
    float* out = (float*)d_out;

    float* hraw;
    __nv_bfloat16 *ah, *al, *bh1, *bl1, *bh2, *bl2, *wp;
    cudaGetSymbolAddress((void**)&hraw, g_hraw);
    cudaGetSymbolAddress((void**)&ah, g_ah);
    cudaGetSymbolAddress((void**)&al, g_al);
    cudaGetSymbolAddress((void**)&bh1, g_bh1);
    cudaGetSymbolAddress((void**)&bl1, g_bl1);
    cudaGetSymbolAddress((void**)&bh2, g_bh2);
    cudaGetSymbolAddress((void**)&bl2, g_bl2);
    cudaGetSymbolAddress((void**)&wp, g_w);

    const int SMEM = 3 * 32768;
    cudaFuncSetAttribute(k_mma<256, 1, 0>, cudaFuncAttributeMaxDynamicSharedMemorySize, SMEM);
    cudaFuncSetAttribute(k_mma<128, 0, 1>, cudaFuncAttributeMaxDynamicSharedMemorySize, SMEM);

    // ---- CSR build ----
    k_init<<<(N_NODES + 255) / 256, 256>>>();
    k_hist<<<(N_EDGES + 255) / 256, 256>>>(dstv);
    int nb = (N_NODES + 1023) / 1024;
    k_scan1<<<nb, 1024>>>();
    k_scan2<<<1, 32>>>(nb);
    k_scan3<<<nb, 1024>>>();
    k_fill<<<(N_EDGES + 255) / 256, 256>>>(srcv, dstv);

    // ---- weight + x conversion (2 launches) ----
    {
        ConvJobs j;
        j.W[0] = wl0; j.K[0] = 128; j.N[0] = 256; j.oh[0] = WL0H; j.ol[0] = WL0L;
        j.W[1] = wr0; j.K[1] = 128; j.N[1] = 256; j.oh[1] = WR0H; j.ol[1] = WR0L;
        j.W[2] = wl1; j.K[2] = 256; j.N[2] = 256; j.oh[2] = WL1H; j.ol[2] = WL1L;
        j.W[3] = wr1; j.K[3] = 256; j.N[3] = 256; j.oh[3] = WR1H; j.ol[3] = WR1L;
        j.W[4] = wl2; j.K[4] = 256; j.N[4] = 256; j.oh[4] = WL2H; j.ol[4] = WL2L;
        j.W[5] = wr2; j.K[5] = 256; j.N[5] = 256; j.oh[5] = WR2H; j.ol[5] = WR2L;
        j.W[6] = cw1; j.K[6] = 256; j.N[6] = 128; j.oh[6] = CW1H; j.ol[6] = CW1L;
        k_convall<<<dim3(256, 7), 256>>>(j, wp);
    }
    k_convx<<<(N_NODES * IN_DIM / 4 + 255) / 256, 256>>>(x, bh2, bl2);

    int aggGrid = (N_NODES * 32 + 255) / 256;
    int nfGrid  = (N_NODES * HID / 4 + 255) / 256;
    int mblocks = (N_NODES + 127) / 128;          // 782
    dim3 gMain(2, mblocks);                       // NT=256
    dim3 gCls(1, mblocks);                        // NT=128

    // ---- layer 0 (D=128): A2 = x (bh2/bl2) ----
    k_agg_f32<<<aggGrid, 256>>>(x, ah, al);
    {
        GemmSegs s;
        s.A[0] = ah;  s.W[0] = wp + WL0H;
        s.A[1] = ah;  s.W[1] = wp + WL0L;
        s.A[2] = al;  s.W[2] = wp + WL0H;
        s.A[3] = bh2; s.W[3] = wp + WR0H;
        s.A[4] = bh2; s.W[4] = wp + WR0L;
        s.A[5] = bl2; s.W[5] = wp + WR0H;
        k_mma<256, 1, 0><<<gMain, 256, SMEM>>>(s, 6, 128, b0, hraw, 0, nullptr, nullptr);
    }
    k_stats<<<1, 256>>>(g0, be0);
    k_normfuse<<<nfGrid, 256>>>(hraw, bh1, bl1);

    // ---- layer 1 (D=256) ----
    k_agg_bf16<<<aggGrid, 256>>>(bh1, bl1, ah, al);
    {
        GemmSegs s;
        s.A[0] = ah;  s.W[0] = wp + WL1H;
        s.A[1] = ah;  s.W[1] = wp + WL1L;
        s.A[2] = al;  s.W[2] = wp + WL1H;
        s.A[3] = bh1; s.W[3] = wp + WR1H;
        s.A[4] = bh1; s.W[4] = wp + WR1L;
        s.A[5] = bl1; s.W[5] = wp + WR1H;
        k_mma<256, 1, 0><<<gMain, 256, SMEM>>>(s, 6, 256, b1, hraw, 0, nullptr, nullptr);
    }
    k_stats<<<1, 256>>>(g1, be1);
    k_normfuse<<<nfGrid, 256>>>(hraw, bh2, bl2);

    // ---- layer 2 (D=256) ----
    k_agg_bf16<<<aggGrid, 256>>>(bh2, bl2, ah, al);
    {
        GemmSegs s;
        s.A[0] = ah;  s.W[0] = wp + WL2H;
        s.A[1] = ah;  s.W[1] = wp + WL2L;
        s.A[2] = al;  s.W[2] = wp + WL2H;
        s.A[3] = bh2; s.W[3] = wp + WR2H;
        s.A[4] = bh2; s.W[4] = wp + WR2L;
        s.A[5] = bl2; s.W[5] = wp + WR2H;
        k_mma<256, 1, 0><<<gMain, 256, SMEM>>>(s, 6, 256, b2, hraw, 0, nullptr, nullptr);
    }
    k_stats<<<1, 256>>>(g2, be2);
    k_normfuse<<<nfGrid, 256>>>(hraw, bh1, bl1);

    // ---- classifier + final head fused: out = relu(h2@cw1+cb1) @ cw2 + cb2 ----
    {
        GemmSegs s;
        s.A[0] = bh1; s.W[0] = wp + CW1H;
        s.A[1] = bh1; s.W[1] = wp + CW1L;
        s.A[2] = bl1; s.W[2] = wp + CW1H;
        s.A[3] = nullptr; s.W[3] = nullptr;
        s.A[4] = nullptr; s.W[4] = nullptr;
        s.A[5] = nullptr; s.W[5] = nullptr;
        k_mma<128, 0, 1><<<gCls, 256, SMEM>>>(s, 3, 256, cb1, out, 1, cw2, cb2);
    }
}

// round 6
// speedup vs baseline: 2.3577x; 1.1191x over previous
#include <cuda_runtime.h>
#include <cuda_bf16.h>
#include <cuda_fp16.h>
#include <cstdint>

#define N_NODES 100000
#define N_EDGES 1600000
#define IN_DIM 128
#define HID 256
#define EPS 1e-5f

// ======================= scratch (static __device__) =======================
__device__ float g_hraw[N_NODES * HID];                 // GEMM output fp32
__device__ __nv_bfloat16 g_ah[N_NODES * HID];           // agg hi
__device__ __nv_bfloat16 g_al[N_NODES * HID];           // agg lo
__device__ __nv_bfloat16 g_bh1[N_NODES * HID];          // buf A hi
__device__ __nv_bfloat16 g_bl1[N_NODES * HID];          // buf A lo
__device__ __nv_bfloat16 g_bh2[N_NODES * HID];          // buf B hi
__device__ __nv_bfloat16 g_bl2[N_NODES * HID];          // buf B lo
__device__ __half g_hf16[N_NODES * HID];                // fp16 gather stream (layers 1/2)
__device__ __nv_bfloat16 g_w[720896];                   // converted weights W^T [N][K] hi/lo
__device__ int   g_cnt[N_NODES];
__device__ int   g_cursor[N_NODES];
__device__ int   g_scantmp[N_NODES];
__device__ int   g_rowptr[N_NODES + 1];
__device__ int   g_adj[N_EDGES];
__device__ int   g_bsum[128];
__device__ float g_colsum[3][HID];
__device__ float g_colsumsq[3][HID];

// weight pool offsets (elements)
#define WL0H 0
#define WL0L 32768
#define WR0H 65536
#define WR0L 98304
#define WL1H 131072
#define WL1L 196608
#define WR1H 262144
#define WR1L 327680
#define WL2H 393216
#define WL2L 458752
#define WR2H 524288
#define WR2L 589824
#define CW1H 655360
#define CW1L 688128

__device__ __forceinline__ uint32_t smem_u32(const void* p) {
    uint32_t a;
    asm("{ .reg .u64 t; cvta.to.shared.u64 t, %1; cvt.u32.u64 %0, t; }" : "=r"(a) : "l"(p));
    return a;
}

// ======================= CSR build =======================
__global__ void k_init() {
    int i = blockIdx.x * blockDim.x + threadIdx.x;
    if (i < N_NODES) { g_cnt[i] = 0; g_cursor[i] = 0; }
    if (i < HID) {
        #pragma unroll
        for (int l = 0; l < 3; l++) { g_colsum[l][i] = 0.f; g_colsumsq[l][i] = 0.f; }
    }
}
__global__ void k_hist(const int* __restrict__ dst) {
    int e = blockIdx.x * blockDim.x + threadIdx.x;
    if (e < N_EDGES) atomicAdd(&g_cnt[dst[e]], 1);
}
__global__ void k_scan1() {
    __shared__ int s[1024];
    int i = blockIdx.x * 1024 + threadIdx.x;
    int v = (i < N_NODES) ? g_cnt[i] : 0;
    s[threadIdx.x] = v;
    __syncthreads();
    #pragma unroll
    for (int off = 1; off < 1024; off <<= 1) {
        int t = (threadIdx.x >= off) ? s[threadIdx.x - off] : 0;
        __syncthreads();
        s[threadIdx.x] += t;
        __syncthreads();
    }
    if (i < N_NODES) g_scantmp[i] = s[threadIdx.x];
    if (threadIdx.x == 1023) g_bsum[blockIdx.x] = s[1023];
}
__global__ void k_scan2(int nb) {
    if (threadIdx.x == 0 && blockIdx.x == 0) {
        int acc = 0;
        for (int i = 0; i < nb; i++) { int v = g_bsum[i]; g_bsum[i] = acc; acc += v; }
    }
}
__global__ void k_scan3() {
    int i = blockIdx.x * 1024 + threadIdx.x;
    if (i < N_NODES) {
        g_rowptr[i + 1] = g_scantmp[i] + g_bsum[blockIdx.x];
        if (i == 0) g_rowptr[0] = 0;
    }
}
__global__ void k_fill(const int* __restrict__ src, const int* __restrict__ dst) {
    int e = blockIdx.x * blockDim.x + threadIdx.x;
    if (e < N_EDGES) {
        int d = dst[e];
        int pos = g_rowptr[d] + atomicAdd(&g_cursor[d], 1);
        g_adj[pos] = src[e];
    }
}

// ======================= pack helpers =======================
__device__ __forceinline__ uint32_t pack2bf(float a, float b) {
    uint16_t ua = __bfloat16_as_ushort(__float2bfloat16(a));
    uint16_t ub = __bfloat16_as_ushort(__float2bfloat16(b));
    return (uint32_t)ua | ((uint32_t)ub << 16);
}
__device__ __forceinline__ float lo_of(float v) {
    return v - __bfloat162float(__float2bfloat16(v));
}

// ======================= aggregation =======================
// Layer 0: fp32 input [N,128] -> agg hi/lo bf16.
__global__ void k_agg_f32(const float* __restrict__ x,
                          __nv_bfloat16* __restrict__ oh, __nv_bfloat16* __restrict__ ol) {
    int w = (blockIdx.x * blockDim.x + threadIdx.x) >> 5;
    int lane = threadIdx.x & 31;
    if (w >= N_NODES) return;
    int s0 = g_rowptr[w], s1 = g_rowptr[w + 1];
    float4 a0 = make_float4(0.f, 0.f, 0.f, 0.f);
    for (int e = s0; e < s1; e++) {
        const float4* p = (const float4*)(x + (size_t)g_adj[e] * IN_DIM);
        float4 v = p[lane];
        a0.x += v.x; a0.y += v.y; a0.z += v.z; a0.w += v.w;
    }
    int deg = s1 - s0;
    float inv = 1.f / (float)(deg > 0 ? deg : 1);
    a0.x *= inv; a0.y *= inv; a0.z *= inv; a0.w *= inv;
    size_t base = (size_t)w * IN_DIM + lane * 4;
    uint2 uh, ul;
    uh.x = pack2bf(a0.x, a0.y); uh.y = pack2bf(a0.z, a0.w);
    ul.x = pack2bf(lo_of(a0.x), lo_of(a0.y)); ul.y = pack2bf(lo_of(a0.z), lo_of(a0.w));
    *(uint2*)(oh + base) = uh;
    *(uint2*)(ol + base) = ul;
}

// Layers 1,2: fp16 input [N,256] -> agg hi/lo bf16. warp per node, lane = 8 cols (16B).
__global__ void k_agg_f16(const __half* __restrict__ xf,
                          __nv_bfloat16* __restrict__ oh, __nv_bfloat16* __restrict__ ol) {
    int w = (blockIdx.x * blockDim.x + threadIdx.x) >> 5;
    int lane = threadIdx.x & 31;
    if (w >= N_NODES) return;
    int s0 = g_rowptr[w], s1 = g_rowptr[w + 1];
    float acc[8];
    #pragma unroll
    for (int i = 0; i < 8; i++) acc[i] = 0.f;
    for (int e = s0; e < s1; e++) {
        size_t base = (size_t)g_adj[e] * HID + lane * 8;
        uint4 v = *(const uint4*)(xf + base);
        const uint32_t* p = &v.x;
        #pragma unroll
        for (int i = 0; i < 4; i++) {
            float2 f = __half22float2(*(const __half2*)&p[i]);
            acc[i * 2 + 0] += f.x;
            acc[i * 2 + 1] += f.y;
        }
    }
    int deg = s1 - s0;
    float inv = 1.f / (float)(deg > 0 ? deg : 1);
    uint4 uh, ul;
    uint32_t* ph = &uh.x; uint32_t* pl = &ul.x;
    #pragma unroll
    for (int i = 0; i < 4; i++) {
        float v0 = acc[i * 2] * inv, v1 = acc[i * 2 + 1] * inv;
        ph[i] = pack2bf(v0, v1);
        pl[i] = pack2bf(lo_of(v0), lo_of(v1));
    }
    size_t base = (size_t)w * HID + lane * 8;
    *(uint4*)(oh + base) = uh;
    *(uint4*)(ol + base) = ul;
}

// ======================= conversions =======================
__global__ void k_convx(const float* __restrict__ x,
                        __nv_bfloat16* __restrict__ oh, __nv_bfloat16* __restrict__ ol) {
    int i = blockIdx.x * blockDim.x + threadIdx.x;   // float4 index
    if (i >= N_NODES * IN_DIM / 4) return;
    float4 v = ((const float4*)x)[i];
    uint2 uh, ul;
    uh.x = pack2bf(v.x, v.y); uh.y = pack2bf(v.z, v.w);
    ul.x = pack2bf(lo_of(v.x), lo_of(v.y)); ul.y = pack2bf(lo_of(v.z), lo_of(v.w));
    ((uint2*)oh)[i] = uh;
    ((uint2*)ol)[i] = ul;
}

// All weights: fp32 [K,N] -> W^T bf16 [N][K] hi/lo, 7 jobs in one launch
struct ConvJobs { const float* W[7]; int K[7]; int N[7]; int oh[7]; int ol[7]; };
__global__ void k_convall(ConvJobs j, __nv_bfloat16* __restrict__ wp) {
    int s = blockIdx.y;
    int K = j.K[s], N = j.N[s];
    int id = blockIdx.x * blockDim.x + threadIdx.x;
    if (id >= K * N) return;
    int k = id / N, n = id % N;
    float v = __ldg(&j.W[s][id]);
    size_t pos = (size_t)n * K + k;
    wp[j.oh[s] + pos] = __float2bfloat16(v);
    wp[j.ol[s] + pos] = __float2bfloat16(lo_of(v));
}

// ======================= bf16 mma.sync GEMM =======================
struct GemmSegs { const __nv_bfloat16* A[6]; const __nv_bfloat16* W[6]; };

#define MMA_BF16(c, a, b0v, b1v) \
    asm volatile("mma.sync.aligned.m16n8k16.row.col.f32.bf16.bf16.f32 " \
        "{%0,%1,%2,%3}, {%4,%5,%6,%7}, {%8,%9}, {%0,%1,%2,%3};" \
        : "+f"((c)[0]), "+f"((c)[1]), "+f"((c)[2]), "+f"((c)[3]) \
        : "r"((a)[0]), "r"((a)[1]), "r"((a)[2]), "r"((a)[3]), "r"(b0v), "r"(b1v))

template <int NT, int STATS, int FINAL>
__global__ __launch_bounds__(256, 2)
void k_mma(GemmSegs segs, int nseg, int D, const float* __restrict__ bias,
           float* __restrict__ C, int relu,
           const float* __restrict__ w2, const float* __restrict__ b2,
           float* __restrict__ csum, float* __restrict__ cqsum) {
    extern __shared__ char dsm[];                 // 3 stages x [A 16KB | B 16KB]
    __shared__ float scol[128], scolq[128];
    __shared__ float srow[256];
    __shared__ float s_w2[256];
    const uint32_t sb = smem_u32(dsm);
    const int tid = threadIdx.x;
    const int lane = tid & 31, wid = tid >> 5;
    const int wm = wid & 3, wn = wid >> 2;        // 4 m-warps x 2 n-warps
    const int bm0 = blockIdx.y * 128, bn0 = blockIdx.x * 128;
    const int grp = lane >> 3, tg = lane & 7;

    if (STATS && tid < 128) { scol[tid] = 0.f; scolq[tid] = 0.f; }
    if (FINAL && tid < 256) { srow[tid] = 0.f; s_w2[tid] = __ldg(&w2[tid]); }

    const int cpsLog = (D == 256) ? 2 : 1;        // k64-blocks per segment (log2)
    const int nkb = nseg << cpsLog;

    // ldmatrix per-thread geometry (XOR-swizzled 128B rows)
    const uint32_t xr = (uint32_t)tg << 4;
    const int rowA0 = wm * 32 + tg + (grp & 1) * 8;
    const int rowB0 = wn * 64 + tg + (grp >> 1) * 8;
    const uint32_t kA = (uint32_t)(grp >> 1) * 16;
    const uint32_t kB = (uint32_t)(grp & 1) * 16;

    float acc[2][8][4];
    #pragma unroll
    for (int mt = 0; mt < 2; mt++)
        #pragma unroll
        for (int nt = 0; nt < 8; nt++)
            #pragma unroll
            for (int j = 0; j < 4; j++) acc[mt][nt][j] = 0.f;

    auto load_stage = [&](int kb, int st) {
        int seg = kb >> cpsLog;
        int koff = (kb & ((1 << cpsLog) - 1)) << 6;
        const __nv_bfloat16* Aseg = segs.A[seg];
        const __nv_bfloat16* Wseg = segs.W[seg];
        uint32_t sA = sb + (uint32_t)st * 32768u;
        uint32_t sB = sA + 16384u;
        #pragma unroll
        for (int t = 0; t < 4; t++) {
            int idx = tid + t * 256;
            int row = idx >> 3, ch = idx & 7;
            uint32_t swz = (uint32_t)row * 128u + (((uint32_t)ch * 16u) ^ (((uint32_t)row & 7u) << 4));
            int grow = bm0 + row;
            int ok = grow < N_NODES;
            const void* gA = Aseg + (size_t)(ok ? grow : 0) * D + koff + ch * 8;
            int sz = ok ? 16 : 0;
            asm volatile("cp.async.cg.shared.global [%0], [%1], 16, %2;"
                         :: "r"(sA + swz), "l"(gA), "r"(sz));
            const void* gB = Wseg + (size_t)(bn0 + row) * D + koff + ch * 8;
            asm volatile("cp.async.cg.shared.global [%0], [%1], 16;"
                         :: "r"(sB + swz), "l"(gB));
        }
        asm volatile("cp.async.commit_group;");
    };

    auto compute_stage = [&](int st) {
        uint32_t aBase = sb + (uint32_t)st * 32768u + (uint32_t)rowA0 * 128u;
        uint32_t bBase = sb + (uint32_t)st * 32768u + 16384u + (uint32_t)rowB0 * 128u;
        #pragma unroll
        for (int kt = 0; kt < 4; kt++) {
            uint32_t a[2][4];
            #pragma unroll
            for (int mt = 0; mt < 2; mt++) {
                uint32_t ad = aBase + (uint32_t)mt * 2048u + (((uint32_t)kt * 32u + kA) ^ xr);
                asm volatile("ldmatrix.sync.aligned.m8n8.x4.shared.b16 {%0,%1,%2,%3}, [%4];"
                    : "=r"(a[mt][0]), "=r"(a[mt][1]), "=r"(a[mt][2]), "=r"(a[mt][3]) : "r"(ad));
            }
            #pragma unroll
            for (int np = 0; np < 4; np++) {
                uint32_t b0, b1, b2r, b3;
                uint32_t bd = bBase + (uint32_t)np * 2048u + (((uint32_t)kt * 32u + kB) ^ xr);
                asm volatile("ldmatrix.sync.aligned.m8n8.x4.shared.b16 {%0,%1,%2,%3}, [%4];"
                    : "=r"(b0), "=r"(b1), "=r"(b2r), "=r"(b3) : "r"(bd));
                #pragma unroll
                for (int mt = 0; mt < 2; mt++) {
                    MMA_BF16(acc[mt][np * 2 + 0], a[mt], b0, b1);
                    MMA_BF16(acc[mt][np * 2 + 1], a[mt], b2r, b3);
                }
            }
        }
    };

    // ---- 3-stage pipelined main loop ----
    load_stage(0, 0);
    load_stage(1, 1);
    int st = 0;
    for (int kb = 0; kb < nkb; kb++) {
        if (kb < nkb - 1) asm volatile("cp.async.wait_group 1;");
        else              asm volatile("cp.async.wait_group 0;");
        __syncthreads();
        compute_stage(st);
        if (kb + 2 < nkb) {
            int st2 = st + 2; if (st2 >= 3) st2 -= 3;
            load_stage(kb + 2, st2);
        }
        if (++st == 3) st = 0;
    }

    // ---- epilogue ----
    const int rbase = wm * 32 + (lane >> 2);
    const int cbL = wn * 64 + (lane & 3) * 2;     // local col
    float po[8];
    #pragma unroll
    for (int i = 0; i < 8; i++) po[i] = 0.f;

    #pragma unroll
    for (int nt = 0; nt < 8; nt++) {
        int colL = cbL + nt * 8;
        int col = bn0 + colL;
        float bv0 = __ldg(&bias[col]), bv1 = __ldg(&bias[col + 1]);
        float s0 = 0.f, s1 = 0.f, q0 = 0.f, q1 = 0.f;
        #pragma unroll
        for (int mt = 0; mt < 2; mt++) {
            int row = bm0 + rbase + mt * 16;
            float h0 = acc[mt][nt][0] + bv0, h1 = acc[mt][nt][1] + bv1;
            float h2 = acc[mt][nt][2] + bv0, h3 = acc[mt][nt][3] + bv1;
            if (relu) {
                h0 = fmaxf(h0, 0.f); h1 = fmaxf(h1, 0.f);
                h2 = fmaxf(h2, 0.f); h3 = fmaxf(h3, 0.f);
            }
            bool v0 = row < N_NODES, v1 = (row + 8) < N_NODES;
            if (STATS) {
                float a0 = v0 ? h0 : 0.f, a1 = v0 ? h1 : 0.f;
                float a2 = v1 ? h2 : 0.f, a3 = v1 ? h3 : 0.f;
                s0 += a0 + a2; s1 += a1 + a3;
                q0 += a0 * a0 + a2 * a2; q1 += a1 * a1 + a3 * a3;
            }
            if (!FINAL) {
                if (v0) *(float2*)(C + (size_t)row * NT + col) = make_float2(h0, h1);
                if (v1) *(float2*)(C + (size_t)(row + 8) * NT + col) = make_float2(h2, h3);
            } else {
                float w20 = s_w2[colL * 2], w21 = s_w2[colL * 2 + 1];
                float w30 = s_w2[(colL + 1) * 2], w31 = s_w2[(colL + 1) * 2 + 1];
                po[mt * 4 + 0] += h0 * w20 + h1 * w30;
                po[mt * 4 + 1] += h0 * w21 + h1 * w31;
                po[mt * 4 + 2] += h2 * w20 + h3 * w30;
                po[mt * 4 + 3] += h2 * w21 + h3 * w31;
            }
        }
        if (STATS) {
            #pragma unroll
            for (int off = 4; off <= 16; off <<= 1) {
                s0 += __shfl_xor_sync(0xffffffffu, s0, off);
                s1 += __shfl_xor_sync(0xffffffffu, s1, off);
                q0 += __shfl_xor_sync(0xffffffffu, q0, off);
                q1 += __shfl_xor_sync(0xffffffffu, q1, off);
            }
            if ((lane >> 2) == 0) {
                atomicAdd(&scol[colL], s0);  atomicAdd(&scol[colL + 1], s1);
                atomicAdd(&scolq[colL], q0); atomicAdd(&scolq[colL + 1], q1);
            }
        }
    }
    if (STATS) {
        __syncthreads();
        if (tid < 128) {
            atomicAdd(&csum[bn0 + tid], scol[tid]);
            atomicAdd(&cqsum[bn0 + tid], scolq[tid]);
        }
    }
    if (FINAL) {
        #pragma unroll
        for (int mt = 0; mt < 2; mt++) {
            int rl = rbase + mt * 16;
            atomicAdd(&srow[rl * 2 + 0], po[mt * 4 + 0]);
            atomicAdd(&srow[rl * 2 + 1], po[mt * 4 + 1]);
            atomicAdd(&srow[(rl + 8) * 2 + 0], po[mt * 4 + 2]);
            atomicAdd(&srow[(rl + 8) * 2 + 1], po[mt * 4 + 3]);
        }
        __syncthreads();
        if (tid < 128) {
            int grow = bm0 + tid;
            if (grow < N_NODES) {
                C[(size_t)grow * 2 + 0] = srow[tid * 2 + 0] + __ldg(&b2[0]);
                C[(size_t)grow * 2 + 1] = srow[tid * 2 + 1] + __ldg(&b2[1]);
            }
        }
    }
}

// ======== normalize + relu + hi/lo bf16 + fp16; BN affine computed inline ========
// Each block: 256 threads, 4 float4 per thread (1024 float4s per block).
__global__ void k_normfuse(const float* __restrict__ h,
                           const float* __restrict__ g, const float* __restrict__ be,
                           const float* __restrict__ csum, const float* __restrict__ cqsum,
                           __nv_bfloat16* __restrict__ oh, __nv_bfloat16* __restrict__ ol,
                           __half* __restrict__ of) {
    __shared__ float sna[HID], snc[HID];
    int tid = threadIdx.x;
    {
        float cs = csum[tid], cq = cqsum[tid];
        float mu  = cs / (float)N_NODES;
        float var = cq / (float)N_NODES - mu * mu;
        var = fmaxf(var, 0.f);
        float a = __ldg(&g[tid]) * rsqrtf(var + EPS);
        sna[tid] = a;
        snc[tid] = __ldg(&be[tid]) - mu * a;
    }
    __syncthreads();
    #pragma unroll
    for (int pass = 0; pass < 4; pass++) {
        int i = blockIdx.x * 1024 + pass * 256 + tid;    // float4 index
        if (i >= N_NODES * HID / 4) return;
        float4 v = ((const float4*)h)[i];
        int cidx = (i * 4) & (HID - 1);
        v.x = fmaxf(v.x * sna[cidx + 0] + snc[cidx + 0], 0.f);
        v.y = fmaxf(v.y * sna[cidx + 1] + snc[cidx + 1], 0.f);
        v.z = fmaxf(v.z * sna[cidx + 2] + snc[cidx + 2], 0.f);
        v.w = fmaxf(v.w * sna[cidx + 3] + snc[cidx + 3], 0.f);
        uint2 uh, ul;
        uh.x = pack2bf(v.x, v.y); uh.y = pack2bf(v.z, v.w);
        ul.x = pack2bf(lo_of(v.x), lo_of(v.y)); ul.y = pack2bf(lo_of(v.z), lo_of(v.w));
        ((uint2*)oh)[i] = uh;
        ((uint2*)ol)[i] = ul;
        __half2 f0 = __floats2half2_rn(v.x, v.y);
        __half2 f1 = __floats2half2_rn(v.z, v.w);
        uint2 uf;
        uf.x = *(uint32_t*)&f0; uf.y = *(uint32_t*)&f1;
        ((uint2*)of)[i] = uf;
    }
}

// ======================= launch =======================
extern "C" void kernel_launch(void* const* d_in, const int* in_sizes, int n_in,
                              void* d_out, int out_size) {
    const float* x    = (const float*)d_in[0];
    const int*   ei   = (const int*)d_in[1];   // int32 (JAX x64 disabled)
    const int*   srcv = ei;
    const int*   dstv = ei + N_EDGES;
    const float* wl0 = (const float*)d_in[2];
    const float* wr0 = (const float*)d_in[3];
    const float* b0  = (const float*)d_in[4];
    const float* g0  = (const float*)d_in[5];
    const float* be0 = (const float*)d_in[6];
    const float* wl1 = (const float*)d_in[7];
    const float* wr1 = (const float*)d_in[8];
    const float* b1  = (const float*)d_in[9];
    const float* g1  = (const float*)d_in[10];
    const float* be1 = (const float*)d_in[11];
    const float* wl2 = (const float*)d_in[12];
    const float* wr2 = (const float*)d_in[13];
    const float* b2  = (const float*)d_in[14];
    const float* g2  = (const float*)d_in[15];
    const float* be2 = (const float*)d_in[16];
    const float* cw1 = (const float*)d_in[17];
    const float* cb1 = (const float*)d_in[18];
    const float* cw2 = (const float*)d_in[19];
    const float* cb2 = (const float*)d_in[20];
    float* out = (float*)d_out;

    float* hraw;
    __nv_bfloat16 *ah, *al, *bh1, *bl1, *bh2, *bl2, *wp;
    __half* hf16;
    float *cs, *cq;
    cudaGetSymbolAddress((void**)&hraw, g_hraw);
    cudaGetSymbolAddress((void**)&ah, g_ah);
    cudaGetSymbolAddress((void**)&al, g_al);
    cudaGetSymbolAddress((void**)&bh1, g_bh1);
    cudaGetSymbolAddress((void**)&bl1, g_bl1);
    cudaGetSymbolAddress((void**)&bh2, g_bh2);
    cudaGetSymbolAddress((void**)&bl2, g_bl2);
    cudaGetSymbolAddress((void**)&wp, g_w);
    cudaGetSymbolAddress((void**)&hf16, g_hf16);
    cudaGetSymbolAddress((void**)&cs, g_colsum);
    cudaGetSymbolAddress((void**)&cq, g_colsumsq);

    const int SMEM = 3 * 32768;
    cudaFuncSetAttribute(k_mma<256, 1, 0>, cudaFuncAttributeMaxDynamicSharedMemorySize, SMEM);
    cudaFuncSetAttribute(k_mma<128, 0, 1>, cudaFuncAttributeMaxDynamicSharedMemorySize, SMEM);

    // ---- CSR build ----
    k_init<<<(N_NODES + 255) / 256, 256>>>();
    k_hist<<<(N_EDGES + 255) / 256, 256>>>(dstv);
    int nb = (N_NODES + 1023) / 1024;
    k_scan1<<<nb, 1024>>>();
    k_scan2<<<1, 32>>>(nb);
    k_scan3<<<nb, 1024>>>();
    k_fill<<<(N_EDGES + 255) / 256, 256>>>(srcv, dstv);

    // ---- weight + x conversion ----
    {
        ConvJobs j;
        j.W[0] = wl0; j.K[0] = 128; j.N[0] = 256; j.oh[0] = WL0H; j.ol[0] = WL0L;
        j.W[1] = wr0; j.K[1] = 128; j.N[1] = 256; j.oh[1] = WR0H; j.ol[1] = WR0L;
        j.W[2] = wl1; j.K[2] = 256; j.N[2] = 256; j.oh[2] = WL1H; j.ol[2] = WL1L;
        j.W[3] = wr1; j.K[3] = 256; j.N[3] = 256; j.oh[3] = WR1H; j.ol[3] = WR1L;
        j.W[4] = wl2; j.K[4] = 256; j.N[4] = 256; j.oh[4] = WL2H; j.ol[4] = WL2L;
        j.W[5] = wr2; j.K[5] = 256; j.N[5] = 256; j.oh[5] = WR2H; j.ol[5] = WR2L;
        j.W[6] = cw1; j.K[6] = 256; j.N[6] = 128; j.oh[6] = CW1H; j.ol[6] = CW1L;
        k_convall<<<dim3(256, 7), 256>>>(j, wp);
    }
    k_convx<<<(N_NODES * IN_DIM / 4 + 255) / 256, 256>>>(x, bh2, bl2);

    int aggGrid = (N_NODES * 32 + 255) / 256;
    int nfGrid  = (N_NODES * HID / 4 + 1023) / 1024;
    int mblocks = (N_NODES + 127) / 128;          // 782
    dim3 gMain(2, mblocks);                       // NT=256
    dim3 gCls(1, mblocks);                        // NT=128

    // ---- layer 0 (D=128): A2 = x (bh2/bl2) ----
    k_agg_f32<<<aggGrid, 256>>>(x, ah, al);
    {
        GemmSegs s;
        s.A[0] = ah;  s.W[0] = wp + WL0H;
        s.A[1] = ah;  s.W[1] = wp + WL0L;
        s.A[2] = al;  s.W[2] = wp + WL0H;
        s.A[3] = bh2; s.W[3] = wp + WR0H;
        s.A[4] = bh2; s.W[4] = wp + WR0L;
        s.A[5] = bl2; s.W[5] = wp + WR0H;
        k_mma<256, 1, 0><<<gMain, 256, SMEM>>>(s, 6, 128, b0, hraw, 0, nullptr, nullptr,
                                               cs + 0 * HID, cq + 0 * HID);
    }
    k_normfuse<<<nfGrid, 256>>>(hraw, g0, be0, cs + 0 * HID, cq + 0 * HID, bh1, bl1, hf16);

    // ---- layer 1 (D=256): agg from fp16 stream ----
    k_agg_f16<<<aggGrid, 256>>>(hf16, ah, al);
    {
        GemmSegs s;
        s.A[0] = ah;  s.W[0] = wp + WL1H;
        s.A[1] = ah;  s.W[1] = wp + WL1L;
        s.A[2] = al;  s.W[2] = wp + WL1H;
        s.A[3] = bh1; s.W[3] = wp + WR1H;
        s.A[4] = bh1; s.W[4] = wp + WR1L;
        s.A[5] = bl1; s.W[5] = wp + WR1H;
        k_mma<256, 1, 0><<<gMain, 256, SMEM>>>(s, 6, 256, b1, hraw, 0, nullptr, nullptr,
                                               cs + 1 * HID, cq + 1 * HID);
    }
    k_normfuse<<<nfGrid, 256>>>(hraw, g1, be1, cs + 1 * HID, cq + 1 * HID, bh2, bl2, hf16);

    // ---- layer 2 (D=256): agg from fp16 stream ----
    k_agg_f16<<<aggGrid, 256>>>(hf16, ah, al);
    {
        GemmSegs s;
        s.A[0] = ah;  s.W[0] = wp + WL2H;
        s.A[1] = ah;  s.W[1] = wp + WL2L;
        s.A[2] = al;  s.W[2] = wp + WL2H;
        s.A[3] = bh2; s.W[3] = wp + WR2H;
        s.A[4] = bh2; s.W[4] = wp + WR2L;
        s.A[5] = bl2; s.W[5] = wp + WR2H;
        k_mma<256, 1, 0><<<gMain, 256, SMEM>>>(s, 6, 256, b2, hraw, 0, nullptr, nullptr,
                                               cs + 2 * HID, cq + 2 * HID);
    }
    k_normfuse<<<nfGrid, 256>>>(hraw, g2, be2, cs + 2 * HID, cq + 2 * HID, bh1, bl1, hf16);

    // ---- classifier + final head fused: out = relu(h2@cw1+cb1) @ cw2 + cb2 ----
    {
        GemmSegs s;
        s.A[0] = bh1; s.W[0] = wp + CW1H;
        s.A[1] = bh1; s.W[1] = wp + CW1L;
        s.A[2] = bl1; s.W[2] = wp + CW1H;
        s.A[3] = nullptr; s.W[3] = nullptr;
        s.A[4] = nullptr; s.W[4] = nullptr;
        s.A[5] = nullptr; s.W[5] = nullptr;
        k_mma<128, 0, 1><<<gCls, 256, SMEM>>>(s, 3, 256, cb1, out, 1, cw2, cb2, nullptr, nullptr);
    }
}

// round 7
// speedup vs baseline: 2.8533x; 1.2102x over previous
#include <cuda_runtime.h>
#include <cuda_bf16.h>
#include <cuda_fp16.h>
#include <cstdint>

#define N_NODES 100000
#define N_EDGES 1600000
#define IN_DIM 128
#define HID 256
#define EPS 1e-5f

// ======================= scratch (static __device__) =======================
__device__ float g_hraw[N_NODES * HID];                 // GEMM output fp32
__device__ __nv_bfloat16 g_ah[N_NODES * HID];           // aggf16 [N,256] (fp16, reinterpreted) / L0 agg
__device__ __nv_bfloat16 g_al[N_NODES * HID];           // xf16 [N,128] fp16 (reinterpreted)
__device__ __nv_bfloat16 g_bh1[N_NODES * HID];          // L0 agg hi / L2 h_norm hi
__device__ __nv_bfloat16 g_bl1[N_NODES * HID];          // L0 agg lo / L2 h_norm lo
__device__ __nv_bfloat16 g_bh2[N_NODES * HID];          // x hi (bf16)
__device__ __nv_bfloat16 g_bl2[N_NODES * HID];          // x lo (bf16)
__device__ __half g_hf16[N_NODES * HID];                // fp16 h_norm stream (L0/L1 outputs)
__device__ __nv_bfloat16 g_w[720896];                   // bf16 weight pool
__device__ __half g_wf[524288];                         // fp16 weight pool (L1/L2)
__device__ int   g_cnt[N_NODES];
__device__ int   g_cursor[N_NODES];
__device__ int   g_scantmp[N_NODES];
__device__ int   g_rowptr[N_NODES + 1];
__device__ int   g_adj[N_EDGES];
__device__ int   g_bsum[128];
__device__ float g_colsum[3][HID];
__device__ float g_colsumsq[3][HID];

// bf16 pool offsets
#define WL0H 0
#define WL0L 32768
#define WR0H 65536
#define WR0L 98304
#define CW1H 131072
#define CW1L 163840
// fp16 pool offsets
#define WF1LH 0
#define WF1LL 65536
#define WF1RH 131072
#define WF1RL 196608
#define WF2LH 262144
#define WF2LL 327680
#define WF2RH 393216
#define WF2RL 458752

__device__ __forceinline__ uint32_t smem_u32(const void* p) {
    uint32_t a;
    asm("{ .reg .u64 t; cvta.to.shared.u64 t, %1; cvt.u32.u64 %0, t; }" : "=r"(a) : "l"(p));
    return a;
}

// ======================= CSR build =======================
__global__ void k_init() {
    int i = blockIdx.x * blockDim.x + threadIdx.x;
    if (i < N_NODES) { g_cnt[i] = 0; g_cursor[i] = 0; }
    if (i < HID) {
        #pragma unroll
        for (int l = 0; l < 3; l++) { g_colsum[l][i] = 0.f; g_colsumsq[l][i] = 0.f; }
    }
}
__global__ void k_hist(const int* __restrict__ dst) {
    int e = blockIdx.x * blockDim.x + threadIdx.x;
    if (e < N_EDGES) atomicAdd(&g_cnt[dst[e]], 1);
}
__global__ void k_scan1() {
    __shared__ int s[1024];
    int i = blockIdx.x * 1024 + threadIdx.x;
    int v = (i < N_NODES) ? g_cnt[i] : 0;
    s[threadIdx.x] = v;
    __syncthreads();
    #pragma unroll
    for (int off = 1; off < 1024; off <<= 1) {
        int t = (threadIdx.x >= off) ? s[threadIdx.x - off] : 0;
        __syncthreads();
        s[threadIdx.x] += t;
        __syncthreads();
    }
    if (i < N_NODES) g_scantmp[i] = s[threadIdx.x];
    if (threadIdx.x == 1023) g_bsum[blockIdx.x] = s[1023];
}
__global__ void k_scan2(int nb) {
    if (threadIdx.x == 0 && blockIdx.x == 0) {
        int acc = 0;
        for (int i = 0; i < nb; i++) { int v = g_bsum[i]; g_bsum[i] = acc; acc += v; }
    }
}
__global__ void k_scan3() {
    int i = blockIdx.x * 1024 + threadIdx.x;
    if (i < N_NODES) {
        g_rowptr[i + 1] = g_scantmp[i] + g_bsum[blockIdx.x];
        if (i == 0) g_rowptr[0] = 0;
    }
}
__global__ void k_fill(const int* __restrict__ src, const int* __restrict__ dst) {
    int e = blockIdx.x * blockDim.x + threadIdx.x;
    if (e < N_EDGES) {
        int d = dst[e];
        int pos = g_rowptr[d] + atomicAdd(&g_cursor[d], 1);
        g_adj[pos] = src[e];
    }
}

// ======================= pack helpers =======================
__device__ __forceinline__ uint32_t pack2bf(float a, float b) {
    uint16_t ua = __bfloat16_as_ushort(__float2bfloat16(a));
    uint16_t ub = __bfloat16_as_ushort(__float2bfloat16(b));
    return (uint32_t)ua | ((uint32_t)ub << 16);
}
__device__ __forceinline__ float lo_of(float v) {
    return v - __bfloat162float(__float2bfloat16(v));
}

// ======================= aggregation =======================
// L0: fp16 x [N,128] gather -> hi/lo bf16 [N,128]. warp/node, lane = 4 cols.
__global__ void k_agg16_128(const __half* __restrict__ xf,
                            __nv_bfloat16* __restrict__ oh, __nv_bfloat16* __restrict__ ol) {
    int w = (blockIdx.x * blockDim.x + threadIdx.x) >> 5;
    int lane = threadIdx.x & 31;
    if (w >= N_NODES) return;
    int s0 = g_rowptr[w], s1 = g_rowptr[w + 1];
    float a0 = 0.f, a1 = 0.f, a2 = 0.f, a3 = 0.f;
    for (int e = s0; e < s1; e++) {
        uint2 v = *(const uint2*)(xf + (size_t)g_adj[e] * IN_DIM + lane * 4);
        float2 f0 = __half22float2(*(const __half2*)&v.x);
        float2 f1 = __half22float2(*(const __half2*)&v.y);
        a0 += f0.x; a1 += f0.y; a2 += f1.x; a3 += f1.y;
    }
    int deg = s1 - s0;
    float inv = 1.f / (float)(deg > 0 ? deg : 1);
    a0 *= inv; a1 *= inv; a2 *= inv; a3 *= inv;
    size_t base = (size_t)w * IN_DIM + lane * 4;
    uint2 uh, ul;
    uh.x = pack2bf(a0, a1); uh.y = pack2bf(a2, a3);
    ul.x = pack2bf(lo_of(a0), lo_of(a1)); ul.y = pack2bf(lo_of(a2), lo_of(a3));
    *(uint2*)(oh + base) = uh;
    *(uint2*)(ol + base) = ul;
}

// L1/L2: fp16 [N,256] gather -> fp16 [N,256]. warp/node, lane = 8 cols.
__global__ void k_agg16_256(const __half* __restrict__ xf, __half* __restrict__ o16) {
    int w = (blockIdx.x * blockDim.x + threadIdx.x) >> 5;
    int lane = threadIdx.x & 31;
    if (w >= N_NODES) return;
    int s0 = g_rowptr[w], s1 = g_rowptr[w + 1];
    float acc[8];
    #pragma unroll
    for (int i = 0; i < 8; i++) acc[i] = 0.f;
    for (int e = s0; e < s1; e++) {
        size_t base = (size_t)g_adj[e] * HID + lane * 8;
        uint4 v = *(const uint4*)(xf + base);
        const uint32_t* p = &v.x;
        #pragma unroll
        for (int i = 0; i < 4; i++) {
            float2 f = __half22float2(*(const __half2*)&p[i]);
            acc[i * 2 + 0] += f.x;
            acc[i * 2 + 1] += f.y;
        }
    }
    int deg = s1 - s0;
    float inv = 1.f / (float)(deg > 0 ? deg : 1);
    uint4 u;
    uint32_t* p = &u.x;
    #pragma unroll
    for (int i = 0; i < 4; i++) {
        __half2 h = __floats2half2_rn(acc[i * 2] * inv, acc[i * 2 + 1] * inv);
        p[i] = *(uint32_t*)&h;
    }
    *(uint4*)(o16 + (size_t)w * HID + lane * 8) = u;
}

// ======================= conversions =======================
// x fp32 [N,128] -> bf16 hi/lo + fp16
__global__ void k_convx(const float* __restrict__ x,
                        __nv_bfloat16* __restrict__ oh, __nv_bfloat16* __restrict__ ol,
                        __half* __restrict__ o16) {
    int i = blockIdx.x * blockDim.x + threadIdx.x;   // float4 index
    if (i >= N_NODES * IN_DIM / 4) return;
    float4 v = ((const float4*)x)[i];
    uint2 uh, ul, uf;
    uh.x = pack2bf(v.x, v.y); uh.y = pack2bf(v.z, v.w);
    ul.x = pack2bf(lo_of(v.x), lo_of(v.y)); ul.y = pack2bf(lo_of(v.z), lo_of(v.w));
    __half2 f0 = __floats2half2_rn(v.x, v.y);
    __half2 f1 = __floats2half2_rn(v.z, v.w);
    uf.x = *(uint32_t*)&f0; uf.y = *(uint32_t*)&f1;
    ((uint2*)oh)[i] = uh;
    ((uint2*)ol)[i] = ul;
    ((uint2*)o16)[i] = uf;
}

// weights: mode 0 -> bf16 hi/lo into wp; mode 1 -> fp16 hi/lo into wf. W^T [N][K].
struct ConvJobs { const float* W[7]; int K[7]; int N[7]; int oh[7]; int ol[7]; int mode[7]; };
__global__ void k_convall(ConvJobs j, __nv_bfloat16* __restrict__ wp, __half* __restrict__ wf) {
    int s = blockIdx.y;
    int K = j.K[s], N = j.N[s];
    int id = blockIdx.x * blockDim.x + threadIdx.x;
    if (id >= K * N) return;
    int k = id / N, n = id % N;
    float v = __ldg(&j.W[s][id]);
    size_t pos = (size_t)n * K + k;
    if (j.mode[s] == 0) {
        wp[j.oh[s] + pos] = __float2bfloat16(v);
        wp[j.ol[s] + pos] = __float2bfloat16(lo_of(v));
    } else {
        __half h = __float2half_rn(v);
        wf[j.oh[s] + pos] = h;
        wf[j.ol[s] + pos] = __float2half_rn(v - __half2float(h));
    }
}

// ======================= mma.sync GEMM (bf16 or f16) =======================
struct GemmSegs { const void* A[6]; const void* W[6]; };

#define MMA_BF16(c, a, b0v, b1v) \
    asm volatile("mma.sync.aligned.m16n8k16.row.col.f32.bf16.bf16.f32 " \
        "{%0,%1,%2,%3}, {%4,%5,%6,%7}, {%8,%9}, {%0,%1,%2,%3};" \
        : "+f"((c)[0]), "+f"((c)[1]), "+f"((c)[2]), "+f"((c)[3]) \
        : "r"((a)[0]), "r"((a)[1]), "r"((a)[2]), "r"((a)[3]), "r"(b0v), "r"(b1v))
#define MMA_F16(c, a, b0v, b1v) \
    asm volatile("mma.sync.aligned.m16n8k16.row.col.f32.f16.f16.f32 " \
        "{%0,%1,%2,%3}, {%4,%5,%6,%7}, {%8,%9}, {%0,%1,%2,%3};" \
        : "+f"((c)[0]), "+f"((c)[1]), "+f"((c)[2]), "+f"((c)[3]) \
        : "r"((a)[0]), "r"((a)[1]), "r"((a)[2]), "r"((a)[3]), "r"(b0v), "r"(b1v))

template <int NT, int STATS, int FINAL, int DT>
__global__ __launch_bounds__(256, 2)
void k_mma(GemmSegs segs, int nseg, int D, const float* __restrict__ bias,
           float* __restrict__ C, int relu,
           const float* __restrict__ w2, const float* __restrict__ b2,
           float* __restrict__ csum, float* __restrict__ cqsum) {
    extern __shared__ char dsm[];                 // 3 stages x [A 16KB | B 16KB]
    __shared__ float scol[128], scolq[128];
    __shared__ float srow[256];
    __shared__ float s_w2[256];
    const uint32_t sb = smem_u32(dsm);
    const int tid = threadIdx.x;
    const int lane = tid & 31, wid = tid >> 5;
    const int wm = wid & 3, wn = wid >> 2;        // 4 m-warps x 2 n-warps
    const int bm0 = blockIdx.y * 128, bn0 = blockIdx.x * 128;
    const int grp = lane >> 3, tg = lane & 7;

    if (STATS && tid < 128) { scol[tid] = 0.f; scolq[tid] = 0.f; }
    if (FINAL && tid < 256) { srow[tid] = 0.f; s_w2[tid] = __ldg(&w2[tid]); }

    const int cpsLog = (D == 256) ? 2 : 1;
    const int nkb = nseg << cpsLog;

    const uint32_t xr = (uint32_t)tg << 4;
    const int rowA0 = wm * 32 + tg + (grp & 1) * 8;
    const int rowB0 = wn * 64 + tg + (grp >> 1) * 8;
    const uint32_t kA = (uint32_t)(grp >> 1) * 16;
    const uint32_t kB = (uint32_t)(grp & 1) * 16;

    float acc[2][8][4];
    #pragma unroll
    for (int mt = 0; mt < 2; mt++)
        #pragma unroll
        for (int nt = 0; nt < 8; nt++)
            #pragma unroll
            for (int j = 0; j < 4; j++) acc[mt][nt][j] = 0.f;

    auto load_stage = [&](int kb, int st) {
        int seg = kb >> cpsLog;
        int koff = (kb & ((1 << cpsLog) - 1)) << 6;
        const uint16_t* Aseg = (const uint16_t*)segs.A[seg];
        const uint16_t* Wseg = (const uint16_t*)segs.W[seg];
        uint32_t sA = sb + (uint32_t)st * 32768u;
        uint32_t sB = sA + 16384u;
        #pragma unroll
        for (int t = 0; t < 4; t++) {
            int idx = tid + t * 256;
            int row = idx >> 3, ch = idx & 7;
            uint32_t swz = (uint32_t)row * 128u + (((uint32_t)ch * 16u) ^ (((uint32_t)row & 7u) << 4));
            int grow = bm0 + row;
            int ok = grow < N_NODES;
            const void* gA = Aseg + (size_t)(ok ? grow : 0) * D + koff + ch * 8;
            int sz = ok ? 16 : 0;
            asm volatile("cp.async.cg.shared.global [%0], [%1], 16, %2;"
                         :: "r"(sA + swz), "l"(gA), "r"(sz));
            const void* gB = Wseg + (size_t)(bn0 + row) * D + koff + ch * 8;
            asm volatile("cp.async.cg.shared.global [%0], [%1], 16;"
                         :: "r"(sB + swz), "l"(gB));
        }
        asm volatile("cp.async.commit_group;");
    };

    auto compute_stage = [&](int st) {
        uint32_t aBase = sb + (uint32_t)st * 32768u + (uint32_t)rowA0 * 128u;
        uint32_t bBase = sb + (uint32_t)st * 32768u + 16384u + (uint32_t)rowB0 * 128u;
        #pragma unroll
        for (int kt = 0; kt < 4; kt++) {
            uint32_t a[2][4];
            #pragma unroll
            for (int mt = 0; mt < 2; mt++) {
                uint32_t ad = aBase + (uint32_t)mt * 2048u + (((uint32_t)kt * 32u + kA) ^ xr);
                asm volatile("ldmatrix.sync.aligned.m8n8.x4.shared.b16 {%0,%1,%2,%3}, [%4];"
                    : "=r"(a[mt][0]), "=r"(a[mt][1]), "=r"(a[mt][2]), "=r"(a[mt][3]) : "r"(ad));
            }
            #pragma unroll
            for (int np = 0; np < 4; np++) {
                uint32_t b0, b1, b2r, b3;
                uint32_t bd = bBase + (uint32_t)np * 2048u + (((uint32_t)kt * 32u + kB) ^ xr);
                asm volatile("ldmatrix.sync.aligned.m8n8.x4.shared.b16 {%0,%1,%2,%3}, [%4];"
                    : "=r"(b0), "=r"(b1), "=r"(b2r), "=r"(b3) : "r"(bd));
                #pragma unroll
                for (int mt = 0; mt < 2; mt++) {
                    if (DT == 0) {
                        MMA_BF16(acc[mt][np * 2 + 0], a[mt], b0, b1);
                        MMA_BF16(acc[mt][np * 2 + 1], a[mt], b2r, b3);
                    } else {
                        MMA_F16(acc[mt][np * 2 + 0], a[mt], b0, b1);
                        MMA_F16(acc[mt][np * 2 + 1], a[mt], b2r, b3);
                    }
                }
            }
        }
    };

    load_stage(0, 0);
    load_stage(1, 1);
    int st = 0;
    for (int kb = 0; kb < nkb; kb++) {
        if (kb < nkb - 1) asm volatile("cp.async.wait_group 1;");
        else              asm volatile("cp.async.wait_group 0;");
        __syncthreads();
        compute_stage(st);
        if (kb + 2 < nkb) {
            int st2 = st + 2; if (st2 >= 3) st2 -= 3;
            load_stage(kb + 2, st2);
        }
        if (++st == 3) st = 0;
    }

    // ---- epilogue ----
    const int rbase = wm * 32 + (lane >> 2);
    const int cbL = wn * 64 + (lane & 3) * 2;
    float po[8];
    #pragma unroll
    for (int i = 0; i < 8; i++) po[i] = 0.f;

    #pragma unroll
    for (int nt = 0; nt < 8; nt++) {
        int colL = cbL + nt * 8;
        int col = bn0 + colL;
        float bv0 = __ldg(&bias[col]), bv1 = __ldg(&bias[col + 1]);
        float s0 = 0.f, s1 = 0.f, q0 = 0.f, q1 = 0.f;
        #pragma unroll
        for (int mt = 0; mt < 2; mt++) {
            int row = bm0 + rbase + mt * 16;
            float h0 = acc[mt][nt][0] + bv0, h1 = acc[mt][nt][1] + bv1;
            float h2 = acc[mt][nt][2] + bv0, h3 = acc[mt][nt][3] + bv1;
            if (relu) {
                h0 = fmaxf(h0, 0.f); h1 = fmaxf(h1, 0.f);
                h2 = fmaxf(h2, 0.f); h3 = fmaxf(h3, 0.f);
            }
            bool v0 = row < N_NODES, v1 = (row + 8) < N_NODES;
            if (STATS) {
                float a0 = v0 ? h0 : 0.f, a1 = v0 ? h1 : 0.f;
                float a2 = v1 ? h2 : 0.f, a3 = v1 ? h3 : 0.f;
                s0 += a0 + a2; s1 += a1 + a3;
                q0 += a0 * a0 + a2 * a2; q1 += a1 * a1 + a3 * a3;
            }
            if (!FINAL) {
                if (v0) *(float2*)(C + (size_t)row * NT + col) = make_float2(h0, h1);
                if (v1) *(float2*)(C + (size_t)(row + 8) * NT + col) = make_float2(h2, h3);
            } else {
                float w20 = s_w2[colL * 2], w21 = s_w2[colL * 2 + 1];
                float w30 = s_w2[(colL + 1) * 2], w31 = s_w2[(colL + 1) * 2 + 1];
                po[mt * 4 + 0] += h0 * w20 + h1 * w30;
                po[mt * 4 + 1] += h0 * w21 + h1 * w31;
                po[mt * 4 + 2] += h2 * w20 + h3 * w30;
                po[mt * 4 + 3] += h2 * w21 + h3 * w31;
            }
        }
        if (STATS) {
            #pragma unroll
            for (int off = 4; off <= 16; off <<= 1) {
                s0 += __shfl_xor_sync(0xffffffffu, s0, off);
                s1 += __shfl_xor_sync(0xffffffffu, s1, off);
                q0 += __shfl_xor_sync(0xffffffffu, q0, off);
                q1 += __shfl_xor_sync(0xffffffffu, q1, off);
            }
            if ((lane >> 2) == 0) {
                atomicAdd(&scol[colL], s0);  atomicAdd(&scol[colL + 1], s1);
                atomicAdd(&scolq[colL], q0); atomicAdd(&scolq[colL + 1], q1);
            }
        }
    }
    if (STATS) {
        __syncthreads();
        if (tid < 128) {
            atomicAdd(&csum[bn0 + tid], scol[tid]);
            atomicAdd(&cqsum[bn0 + tid], scolq[tid]);
        }
    }
    if (FINAL) {
        #pragma unroll
        for (int mt = 0; mt < 2; mt++) {
            int rl = rbase + mt * 16;
            atomicAdd(&srow[rl * 2 + 0], po[mt * 4 + 0]);
            atomicAdd(&srow[rl * 2 + 1], po[mt * 4 + 1]);
            atomicAdd(&srow[(rl + 8) * 2 + 0], po[mt * 4 + 2]);
            atomicAdd(&srow[(rl + 8) * 2 + 1], po[mt * 4 + 3]);
        }
        __syncthreads();
        if (tid < 128) {
            int grow = bm0 + tid;
            if (grow < N_NODES) {
                C[(size_t)grow * 2 + 0] = srow[tid * 2 + 0] + __ldg(&b2[0]);
                C[(size_t)grow * 2 + 1] = srow[tid * 2 + 1] + __ldg(&b2[1]);
            }
        }
    }
}

// ======== normalize + relu; OUT=0 -> fp16 only; OUT=1 -> bf16 hi/lo only ========
template <int OUT>
__global__ void k_normfuse(const float* __restrict__ h,
                           const float* __restrict__ g, const float* __restrict__ be,
                           const float* __restrict__ csum, const float* __restrict__ cqsum,
                           __nv_bfloat16* __restrict__ oh, __nv_bfloat16* __restrict__ ol,
                           __half* __restrict__ of) {
    __shared__ float sna[HID], snc[HID];
    int tid = threadIdx.x;
    {
        float cs = csum[tid], cq = cqsum[tid];
        float mu  = cs / (float)N_NODES;
        float var = cq / (float)N_NODES - mu * mu;
        var = fmaxf(var, 0.f);
        float a = __ldg(&g[tid]) * rsqrtf(var + EPS);
        sna[tid] = a;
        snc[tid] = __ldg(&be[tid]) - mu * a;
    }
    __syncthreads();
    #pragma unroll
    for (int pass = 0; pass < 4; pass++) {
        int i = blockIdx.x * 1024 + pass * 256 + tid;    // float4 index
        if (i >= N_NODES * HID / 4) return;
        float4 v = ((const float4*)h)[i];
        int cidx = (i * 4) & (HID - 1);
        v.x = fmaxf(v.x * sna[cidx + 0] + snc[cidx + 0], 0.f);
        v.y = fmaxf(v.y * sna[cidx + 1] + snc[cidx + 1], 0.f);
        v.z = fmaxf(v.z * sna[cidx + 2] + snc[cidx + 2], 0.f);
        v.w = fmaxf(v.w * sna[cidx + 3] + snc[cidx + 3], 0.f);
        if (OUT == 0) {
            __half2 f0 = __floats2half2_rn(v.x, v.y);
            __half2 f1 = __floats2half2_rn(v.z, v.w);
            uint2 uf;
            uf.x = *(uint32_t*)&f0; uf.y = *(uint32_t*)&f1;
            ((uint2*)of)[i] = uf;
        } else {
            uint2 uh, ul;
            uh.x = pack2bf(v.x, v.y); uh.y = pack2bf(v.z, v.w);
            ul.x = pack2bf(lo_of(v.x), lo_of(v.y)); ul.y = pack2bf(lo_of(v.z), lo_of(v.w));
            ((uint2*)oh)[i] = uh;
            ((uint2*)ol)[i] = ul;
        }
    }
}

// ======================= launch =======================
extern "C" void kernel_launch(void* const* d_in, const int* in_sizes, int n_in,
                              void* d_out, int out_size) {
    const float* x    = (const float*)d_in[0];
    const int*   ei   = (const int*)d_in[1];   // int32 (JAX x64 disabled)
    const int*   srcv = ei;
    const int*   dstv = ei + N_EDGES;
    const float* wl0 = (const float*)d_in[2];
    const float* wr0 = (const float*)d_in[3];
    const float* b0  = (const float*)d_in[4];
    const float* g0  = (const float*)d_in[5];
    const float* be0 = (const float*)d_in[6];
    const float* wl1 = (const float*)d_in[7];
    const float* wr1 = (const float*)d_in[8];
    const float* b1  = (const float*)d_in[9];
    const float* g1  = (const float*)d_in[10];
    const float* be1 = (const float*)d_in[11];
    const float* wl2 = (const float*)d_in[12];
    const float* wr2 = (const float*)d_in[13];
    const float* b2  = (const float*)d_in[14];
    const float* g2  = (const float*)d_in[15];
    const float* be2 = (const float*)d_in[16];
    const float* cw1 = (const float*)d_in[17];
    const float* cb1 = (const float*)d_in[18];
    const float* cw2 = (const float*)d_in[19];
    const float* cb2 = (const float*)d_in[20];
    float* out = (float*)d_out;

    float* hraw;
    __nv_bfloat16 *aggbuf, *xfbuf, *bh1, *bl1, *bh2, *bl2, *wp;
    __half *hf16, *wf;
    float *cs, *cq;
    cudaGetSymbolAddress((void**)&hraw, g_hraw);
    cudaGetSymbolAddress((void**)&aggbuf, g_ah);
    cudaGetSymbolAddress((void**)&xfbuf, g_al);
    cudaGetSymbolAddress((void**)&bh1, g_bh1);
    cudaGetSymbolAddress((void**)&bl1, g_bl1);
    cudaGetSymbolAddress((void**)&bh2, g_bh2);
    cudaGetSymbolAddress((void**)&bl2, g_bl2);
    cudaGetSymbolAddress((void**)&wp, g_w);
    cudaGetSymbolAddress((void**)&wf, g_wf);
    cudaGetSymbolAddress((void**)&hf16, g_hf16);
    cudaGetSymbolAddress((void**)&cs, g_colsum);
    cudaGetSymbolAddress((void**)&cq, g_colsumsq);
    __half* aggf16 = (__half*)aggbuf;
    __half* xf16   = (__half*)xfbuf;

    const int SMEM = 3 * 32768;
    cudaFuncSetAttribute(k_mma<256, 1, 0, 0>, cudaFuncAttributeMaxDynamicSharedMemorySize, SMEM);
    cudaFuncSetAttribute(k_mma<256, 1, 0, 1>, cudaFuncAttributeMaxDynamicSharedMemorySize, SMEM);
    cudaFuncSetAttribute(k_mma<128, 0, 1, 0>, cudaFuncAttributeMaxDynamicSharedMemorySize, SMEM);

    // ---- CSR build ----
    k_init<<<(N_NODES + 255) / 256, 256>>>();
    k_hist<<<(N_EDGES + 255) / 256, 256>>>(dstv);
    int nb = (N_NODES + 1023) / 1024;
    k_scan1<<<nb, 1024>>>();
    k_scan2<<<1, 32>>>(nb);
    k_scan3<<<nb, 1024>>>();
    k_fill<<<(N_EDGES + 255) / 256, 256>>>(srcv, dstv);

    // ---- weight + x conversion ----
    {
        ConvJobs j;
        j.W[0] = wl0; j.K[0] = 128; j.N[0] = 256; j.oh[0] = WL0H;  j.ol[0] = WL0L;  j.mode[0] = 0;
        j.W[1] = wr0; j.K[1] = 128; j.N[1] = 256; j.oh[1] = WR0H;  j.ol[1] = WR0L;  j.mode[1] = 0;
        j.W[2] = wl1; j.K[2] = 256; j.N[2] = 256; j.oh[2] = WF1LH; j.ol[2] = WF1LL; j.mode[2] = 1;
        j.W[3] = wr1; j.K[3] = 256; j.N[3] = 256; j.oh[3] = WF1RH; j.ol[3] = WF1RL; j.mode[3] = 1;
        j.W[4] = wl2; j.K[4] = 256; j.N[4] = 256; j.oh[4] = WF2LH; j.ol[4] = WF2LL; j.mode[4] = 1;
        j.W[5] = wr2; j.K[5] = 256; j.N[5] = 256; j.oh[5] = WF2RH; j.ol[5] = WF2RL; j.mode[5] = 1;
        j.W[6] = cw1; j.K[6] = 256; j.N[6] = 128; j.oh[6] = CW1H;  j.ol[6] = CW1L;  j.mode[6] = 0;
        k_convall<<<dim3(256, 7), 256>>>(j, wp, wf);
    }
    k_convx<<<(N_NODES * IN_DIM / 4 + 255) / 256, 256>>>(x, bh2, bl2, xf16);

    int aggGrid = (N_NODES * 32 + 255) / 256;
    int nfGrid  = (N_NODES * HID / 4 + 1023) / 1024;
    int mblocks = (N_NODES + 127) / 128;
    dim3 gMain(2, mblocks);                       // NT=256
    dim3 gCls(1, mblocks);                        // NT=128

    // ---- layer 0 (D=128, bf16 6-seg, exact) ----
    k_agg16_128<<<aggGrid, 256>>>(xf16, bh1, bl1);
    {
        GemmSegs s;
        s.A[0] = bh1; s.W[0] = wp + WL0H;
        s.A[1] = bh1; s.W[1] = wp + WL0L;
        s.A[2] = bl1; s.W[2] = wp + WL0H;
        s.A[3] = bh2; s.W[3] = wp + WR0H;
        s.A[4] = bh2; s.W[4] = wp + WR0L;
        s.A[5] = bl2; s.W[5] = wp + WR0H;
        k_mma<256, 1, 0, 0><<<gMain, 256, SMEM>>>(s, 6, 128, b0, hraw, 0, nullptr, nullptr,
                                                  cs + 0 * HID, cq + 0 * HID);
    }
    k_normfuse<0><<<nfGrid, 256>>>(hraw, g0, be0, cs + 0 * HID, cq + 0 * HID, nullptr, nullptr, hf16);

    // ---- layer 1 (D=256, f16 4-seg) ----
    k_agg16_256<<<aggGrid, 256>>>(hf16, aggf16);
    {
        GemmSegs s;
        s.A[0] = aggf16; s.W[0] = wf + WF1LH;
        s.A[1] = aggf16; s.W[1] = wf + WF1LL;
        s.A[2] = hf16;   s.W[2] = wf + WF1RH;
        s.A[3] = hf16;   s.W[3] = wf + WF1RL;
        s.A[4] = nullptr; s.W[4] = nullptr;
        s.A[5] = nullptr; s.W[5] = nullptr;
        k_mma<256, 1, 0, 1><<<gMain, 256, SMEM>>>(s, 4, 256, b1, hraw, 0, nullptr, nullptr,
                                                  cs + 1 * HID, cq + 1 * HID);
    }
    k_normfuse<0><<<nfGrid, 256>>>(hraw, g1, be1, cs + 1 * HID, cq + 1 * HID, nullptr, nullptr, hf16);

    // ---- layer 2 (D=256, f16 4-seg) ----
    k_agg16_256<<<aggGrid, 256>>>(hf16, aggf16);
    {
        GemmSegs s;
        s.A[0] = aggf16; s.W[0] = wf + WF2LH;
        s.A[1] = aggf16; s.W[1] = wf + WF2LL;
        s.A[2] = hf16;   s.W[2] = wf + WF2RH;
        s.A[3] = hf16;   s.W[3] = wf + WF2RL;
        s.A[4] = nullptr; s.W[4] = nullptr;
        s.A[5] = nullptr; s.W[5] = nullptr;
        k_mma<256, 1, 0, 1><<<gMain, 256, SMEM>>>(s, 4, 256, b2, hraw, 0, nullptr, nullptr,
                                                  cs + 2 * HID, cq + 2 * HID);
    }
    k_normfuse<1><<<nfGrid, 256>>>(hraw, g2, be2, cs + 2 * HID, cq + 2 * HID, bh1, bl1, nullptr);

    // ---- classifier + head fused (bf16 3-seg, exact) ----
    {
        GemmSegs s;
        s.A[0] = bh1; s.W[0] = wp + CW1H;
        s.A[1] = bh1; s.W[1] = wp + CW1L;
        s.A[2] = bl1; s.W[2] = wp + CW1H;
        s.A[3] = nullptr; s.W[3] = nullptr;
        s.A[4] = nullptr; s.W[4] = nullptr;
        s.A[5] = nullptr; s.W[5] = nullptr;
        k_mma<128, 0, 1, 0><<<gCls, 256, SMEM>>>(s, 3, 256, cb1, out, 1, cw2, cb2, nullptr, nullptr);
    }
}